// round 1
// baseline (speedup 1.0000x reference)
#include <cuda_runtime.h>
#include <math.h>

#define Bv    64
#define Pv    196
#define ENCv  2048
#define Ev    512
#define Dv    512
#define Av    512
#define Vv    10000
#define Tv    32
#define NSTEP 31
#define G4D   2048          // 4*D
#define KCAT  3072          // E + ENC + D
#define KSPLIT 8
#define KCHUNK 384          // KCAT / KSPLIT

typedef unsigned long long ull;

// ------------------------- scratch (static device globals) -------------------
__device__ float g_enc_proj[Bv * Pv * Av];     // 25.7 MB
__device__ float g_mean[Bv * ENCv];
__device__ float g_h[Bv * Dv];
__device__ float g_c[Bv * Dv];
__device__ float g_alpha[Bv * Pv];
__device__ float g_context[Bv * ENCv];
__device__ float g_xcat[Bv * KCAT];
__device__ float g_gpart[KSPLIT][Bv * G4D];    // 4 MB

// ------------------------------- helpers -------------------------------------
__device__ __forceinline__ ull pk2(float lo, float hi) {
    ull r; asm("mov.b64 %0, {%1, %2};" : "=l"(r) : "f"(lo), "f"(hi)); return r;
}
__device__ __forceinline__ void fma2(ull& d, ull a, ull b) {
    asm("fma.rn.f32x2 %0, %1, %2, %0;" : "+l"(d) : "l"(a), "l"(b));
}
__device__ __forceinline__ float2 up2(ull v) {
    float lo, hi; asm("mov.b64 {%0, %1}, %2;" : "=f"(lo), "=f"(hi) : "l"(v));
    return make_float2(lo, hi);
}
__device__ __forceinline__ float wsum(float v) {
#pragma unroll
    for (int o = 16; o; o >>= 1) v += __shfl_down_sync(0xffffffffu, v, o);
    return v;
}
__device__ __forceinline__ float sigm(float x) { return 1.0f / (1.0f + expf(-x)); }

// --------------------------- zero last timestep -------------------------------
__global__ void k_zero_tail(float* __restrict__ preds, float* __restrict__ alphas) {
    int idx = blockIdx.x * blockDim.x + threadIdx.x;
    if (idx < Bv * Vv) {
        int b = idx / Vv, v = idx % Vv;
        preds[((size_t)b * Tv + (Tv - 1)) * Vv + v] = 0.0f;
    } else {
        int r = idx - Bv * Vv;
        if (r < Bv * Pv) {
            int b = r / Pv, p = r % Pv;
            alphas[((size_t)b * Tv + (Tv - 1)) * Pv + p] = 0.0f;
        }
    }
}

// -------------------------------- mean over P ---------------------------------
// encoder_out is (B, ENC, P); g_mean[b*ENC+e] = mean_p eo[b,e,p]
__global__ void k_mean(const float* __restrict__ eo) {
    int gw = (blockIdx.x * blockDim.x + threadIdx.x) >> 5;
    int lane = threadIdx.x & 31;
    if (gw >= Bv * ENCv) return;
    const float* row = eo + (size_t)gw * Pv;
    float acc = 0.0f;
    for (int p = lane; p < Pv; p += 32) acc += row[p];
    acc = wsum(acc);
    if (!lane) g_mean[gw] = acc * (1.0f / (float)Pv);
}

// -------------------------------- h0 / c0 -------------------------------------
__global__ void k_init(const float* __restrict__ Wh, const float* __restrict__ bh,
                       const float* __restrict__ Wc, const float* __restrict__ bc) {
    int gw = (blockIdx.x * blockDim.x + threadIdx.x) >> 5;
    int lane = threadIdx.x & 31;
    if (gw >= 2 * Bv * Dv) return;
    int sel = gw >= Bv * Dv;
    int r = gw - sel * Bv * Dv;
    int b = r / Dv, d = r % Dv;
    const float* W = sel ? Wc : Wh;
    const float* mn = g_mean + (size_t)b * ENCv;
    const float* wr = W + (size_t)d * ENCv;
    float acc = 0.0f;
    for (int k = lane; k < ENCv; k += 32) acc += mn[k] * wr[k];
    acc = wsum(acc);
    if (!lane) (sel ? g_c : g_h)[r] = acc + (sel ? bc : bh)[d];
}

// ------------------------------ enc_proj GEMM ---------------------------------
// out[m, a] = sum_e eo[b(m), e, p(m)] * encW[a, e] + encb[a];  m = b*P + p
// 128x64 tile, BK=16, 256 threads, 8x4 per thread with f32x2 accumulation.
__global__ void k_encproj(const float* __restrict__ eo,
                          const float* __restrict__ W,
                          const float* __restrict__ bias) {
    __shared__ float Xs[16][128];
    __shared__ float Ws[16][68];
    int m0 = blockIdx.x * 128;      // 98 tiles, 98*128 = 12544 exact
    int n0 = blockIdx.y * 64;       // 8 tiles
    int tid = threadIdx.x;
    int tx = tid & 15, ty = tid >> 4;

    // hoisted loader indices
    int xkk[8], xmm[8], xoff[8];
#pragma unroll
    for (int r = 0; r < 8; r++) {
        int i = tid + 256 * r;
        xkk[r] = i >> 7;
        xmm[r] = i & 127;
        int m = m0 + xmm[r];
        int b = m / Pv;
        int p = m - b * Pv;
        xoff[r] = b * (ENCv * Pv) + p;
    }
    int wkk[4], wnn[4];
#pragma unroll
    for (int r = 0; r < 4; r++) {
        int i = tid + 256 * r;
        wkk[r] = i & 15;
        wnn[r] = i >> 4;
    }

    ull acc[4][4];
#pragma unroll
    for (int i = 0; i < 4; i++)
#pragma unroll
        for (int j = 0; j < 4; j++) acc[i][j] = 0ull;

    for (int k0 = 0; k0 < ENCv; k0 += 16) {
#pragma unroll
        for (int r = 0; r < 8; r++)
            Xs[xkk[r]][xmm[r]] = eo[xoff[r] + (k0 + xkk[r]) * Pv];
#pragma unroll
        for (int r = 0; r < 4; r++)
            Ws[wkk[r]][wnn[r]] = W[(size_t)(n0 + wnn[r]) * ENCv + k0 + wkk[r]];
        __syncthreads();
#pragma unroll
        for (int k = 0; k < 16; k++) {
            ull a2[4];
#pragma unroll
            for (int i = 0; i < 4; i++)
                a2[i] = *(const ull*)&Xs[k][ty * 8 + 2 * i];
#pragma unroll
            for (int j = 0; j < 4; j++) {
                float bv = Ws[k][tx * 4 + j];
                ull bd = pk2(bv, bv);
#pragma unroll
                for (int i = 0; i < 4; i++) fma2(acc[i][j], a2[i], bd);
            }
        }
        __syncthreads();
    }
#pragma unroll
    for (int j = 0; j < 4; j++) {
        int n = n0 + tx * 4 + j;
        float bb = bias[n];
#pragma unroll
        for (int i = 0; i < 4; i++) {
            float2 v = up2(acc[i][j]);
            int m = m0 + ty * 8 + 2 * i;
            g_enc_proj[(size_t)m * Av + n] = v.x + bb;
            g_enc_proj[(size_t)(m + 1) * Av + n] = v.y + bb;
        }
    }
}

// ------------------------------ attention + softmax ----------------------------
__global__ void k_att(const float* __restrict__ decW, const float* __restrict__ decb,
                      const float* __restrict__ fullW, const float* __restrict__ fullb,
                      float* __restrict__ out_alphas, int t) {
    __shared__ float sh_h[Dv];
    __shared__ float sh_dh[Av];
    __shared__ float sh_fw[Av];
    __shared__ float sh_e[256];
    __shared__ float red[256];
    int b = blockIdx.x;
    int tid = threadIdx.x;
    int w = tid >> 5, lane = tid & 31;

    for (int i = tid; i < Dv; i += 256) sh_h[i] = g_h[b * Dv + i];
    for (int i = tid; i < Av; i += 256) sh_fw[i] = fullW[i];
    __syncthreads();

    // dh = h @ decW.T + decb   (warp per output row, coalesced k)
    for (int a = w; a < Av; a += 8) {
        const float* wr = decW + (size_t)a * Dv;
        float acc = 0.0f;
        for (int k = lane; k < Dv; k += 32) acc += sh_h[k] * wr[k];
        acc = wsum(acc);
        if (!lane) sh_dh[a] = acc + decb[a];
    }
    __syncthreads();

    // e[p] = sum_a relu(enc_proj + dh) * fw
    for (int p = w; p < Pv; p += 8) {
        const float* ep = g_enc_proj + (size_t)(b * Pv + p) * Av;
        float acc = 0.0f;
        for (int k = lane; k < Av; k += 32) {
            float v = ep[k] + sh_dh[k];
            acc += fmaxf(v, 0.0f) * sh_fw[k];
        }
        acc = wsum(acc);
        if (!lane) sh_e[p] = acc + fullb[0];
    }
    __syncthreads();

    // softmax over P=196
    float v = (tid < Pv) ? sh_e[tid] : -3.0e38f;
    red[tid] = v; __syncthreads();
    for (int s = 128; s; s >>= 1) {
        if (tid < s) red[tid] = fmaxf(red[tid], red[tid + s]);
        __syncthreads();
    }
    float mx = red[0]; __syncthreads();
    float ex = (tid < Pv) ? expf(v - mx) : 0.0f;
    red[tid] = ex; __syncthreads();
    for (int s = 128; s; s >>= 1) {
        if (tid < s) red[tid] += red[tid + s];
        __syncthreads();
    }
    float inv = 1.0f / red[0];
    if (tid < Pv) {
        float al = ex * inv;
        g_alpha[b * Pv + tid] = al;
        out_alphas[((size_t)b * Tv + t) * Pv + tid] = al;
    }
}

// ------------------------------ context = alpha @ enc --------------------------
__global__ void k_ctx(const float* __restrict__ eo) {
    __shared__ float sal[Pv];
    int b = blockIdx.y;
    int tid = threadIdx.x;
    int w = tid >> 5, lane = tid & 31;
    if (tid < Pv) sal[tid] = g_alpha[b * Pv + tid];
    __syncthreads();
    int wg = blockIdx.x * 8 + w;  // 0..63 warps per batch element
    const float* base = eo + (size_t)b * ENCv * Pv;
    for (int e = wg; e < ENCv; e += 64) {
        const float* row = base + (size_t)e * Pv;
        float acc = 0.0f;
        for (int p = lane; p < Pv; p += 32) acc += sal[p] * row[p];
        acc = wsum(acc);
        if (!lane) g_context[b * ENCv + e] = acc;
    }
}

// --------------------------- xcat = [emb_t | context | h] ----------------------
__global__ void k_xcat(const int* __restrict__ captions,
                       const float* __restrict__ emb, int t) {
    int b = blockIdx.x;
    int tid = threadIdx.x;
    int cap = captions[b * Tv + t];
    for (int j = tid; j < KCAT; j += 256) {
        float v;
        if (j < Ev)              v = emb[(size_t)cap * Ev + j];
        else if (j < Ev + ENCv)  v = g_context[b * ENCv + (j - Ev)];
        else                     v = g_h[b * Dv + (j - Ev - ENCv)];
        g_xcat[b * KCAT + j] = v;
    }
}

// ------------------------------ gates GEMM (K-split) ---------------------------
// partial[z][b, n] = sum_{k in chunk z} xcat[b,k] * Wcat[n,k]
__global__ void k_gates(const float* __restrict__ Wih, const float* __restrict__ Whh) {
    __shared__ float Xs[16][68];
    __shared__ float Ws[16][68];
    int n0 = blockIdx.x * 64;        // 32 tiles
    int z = blockIdx.y;              // 8 k-chunks
    int kbase = z * KCHUNK;
    int tid = threadIdx.x;
    int tx = tid & 15, ty = tid >> 4;

    ull acc[2][4];
#pragma unroll
    for (int i = 0; i < 2; i++)
#pragma unroll
        for (int j = 0; j < 4; j++) acc[i][j] = 0ull;

    for (int k0 = 0; k0 < KCHUNK; k0 += 16) {
#pragma unroll
        for (int r = 0; r < 4; r++) {
            int i = tid + 256 * r;
            int kk = i & 15;
            int mm = i >> 4;
            int kg = kbase + k0 + kk;
            Xs[kk][mm] = g_xcat[mm * KCAT + kg];
            int n = n0 + mm;
            Ws[kk][mm] = (kg < Ev + ENCv)
                           ? Wih[(size_t)n * (Ev + ENCv) + kg]
                           : Whh[(size_t)n * Dv + (kg - (Ev + ENCv))];
        }
        __syncthreads();
#pragma unroll
        for (int k = 0; k < 16; k++) {
            ull a2[2];
            a2[0] = *(const ull*)&Xs[k][ty * 4];
            a2[1] = *(const ull*)&Xs[k][ty * 4 + 2];
#pragma unroll
            for (int j = 0; j < 4; j++) {
                float bv = Ws[k][tx * 4 + j];
                ull bd = pk2(bv, bv);
                fma2(acc[0][j], a2[0], bd);
                fma2(acc[1][j], a2[1], bd);
            }
        }
        __syncthreads();
    }
#pragma unroll
    for (int j = 0; j < 4; j++) {
        int n = n0 + tx * 4 + j;
#pragma unroll
        for (int i = 0; i < 2; i++) {
            float2 v = up2(acc[i][j]);
            int m = ty * 4 + 2 * i;
            g_gpart[z][m * G4D + n] = v.x;
            g_gpart[z][(m + 1) * G4D + n] = v.y;
        }
    }
}

// ------------------------------ LSTM pointwise ---------------------------------
__global__ void k_lstm(const float* __restrict__ bih, const float* __restrict__ bhh) {
    int idx = blockIdx.x * blockDim.x + threadIdx.x;
    if (idx >= Bv * Dv) return;
    int b = idx / Dv, d = idx % Dv;
    float gi = bih[d] + bhh[d];
    float gf = bih[Dv + d] + bhh[Dv + d];
    float gg = bih[2 * Dv + d] + bhh[2 * Dv + d];
    float go = bih[3 * Dv + d] + bhh[3 * Dv + d];
    int base = b * G4D + d;
#pragma unroll
    for (int z = 0; z < KSPLIT; z++) {
        gi += g_gpart[z][base];
        gf += g_gpart[z][base + Dv];
        gg += g_gpart[z][base + 2 * Dv];
        go += g_gpart[z][base + 3 * Dv];
    }
    float c = g_c[idx];
    float cn = sigm(gf) * c + sigm(gi) * tanhf(gg);
    float hn = sigm(go) * tanhf(cn);
    g_c[idx] = cn;
    g_h[idx] = hn;
}

// ------------------------------ fc GEMM (preds) ---------------------------------
__global__ void k_fc(const float* __restrict__ Wf, const float* __restrict__ bf,
                     float* __restrict__ preds, int t) {
    __shared__ float Xs[16][68];
    __shared__ float Ws[16][68];
    int n0 = blockIdx.x * 64;     // 157 tiles (bounds-checked)
    int tid = threadIdx.x;
    int tx = tid & 15, ty = tid >> 4;

    ull acc[2][4];
#pragma unroll
    for (int i = 0; i < 2; i++)
#pragma unroll
        for (int j = 0; j < 4; j++) acc[i][j] = 0ull;

    for (int k0 = 0; k0 < Dv; k0 += 16) {
#pragma unroll
        for (int r = 0; r < 4; r++) {
            int i = tid + 256 * r;
            int kk = i & 15;
            int mm = i >> 4;
            Xs[kk][mm] = g_h[mm * Dv + k0 + kk];
            int n = n0 + mm;
            Ws[kk][mm] = (n < Vv) ? Wf[(size_t)n * Dv + k0 + kk] : 0.0f;
        }
        __syncthreads();
#pragma unroll
        for (int k = 0; k < 16; k++) {
            ull a2[2];
            a2[0] = *(const ull*)&Xs[k][ty * 4];
            a2[1] = *(const ull*)&Xs[k][ty * 4 + 2];
#pragma unroll
            for (int j = 0; j < 4; j++) {
                float bv = Ws[k][tx * 4 + j];
                ull bd = pk2(bv, bv);
                fma2(acc[0][j], a2[0], bd);
                fma2(acc[1][j], a2[1], bd);
            }
        }
        __syncthreads();
    }
#pragma unroll
    for (int j = 0; j < 4; j++) {
        int n = n0 + tx * 4 + j;
        if (n >= Vv) continue;
        float bb = bf[n];
#pragma unroll
        for (int i = 0; i < 2; i++) {
            float2 v = up2(acc[i][j]);
            int m = ty * 4 + 2 * i;
            preds[((size_t)m * Tv + t) * Vv + n] = v.x + bb;
            preds[((size_t)(m + 1) * Tv + t) * Vv + n] = v.y + bb;
        }
    }
}

// --------------------------------- launcher ------------------------------------
extern "C" void kernel_launch(void* const* d_in, const int* in_sizes, int n_in,
                              void* d_out, int out_size) {
    const float* eo    = (const float*)d_in[0];
    const int*   caps  = (const int*)d_in[1];
    // d_in[2] = lengths (unused; all == T)
    const float* emb   = (const float*)d_in[3];
    const float* encW  = (const float*)d_in[4];
    const float* encb  = (const float*)d_in[5];
    const float* decW  = (const float*)d_in[6];
    const float* decb  = (const float*)d_in[7];
    const float* fullW = (const float*)d_in[8];
    const float* fullb = (const float*)d_in[9];
    const float* ihW   = (const float*)d_in[10];
    const float* ihb   = (const float*)d_in[11];
    const float* icW   = (const float*)d_in[12];
    const float* icb   = (const float*)d_in[13];
    const float* Wih   = (const float*)d_in[14];
    const float* bih   = (const float*)d_in[15];
    const float* Whh   = (const float*)d_in[16];
    const float* bhh   = (const float*)d_in[17];
    const float* fcW   = (const float*)d_in[18];
    const float* fcb   = (const float*)d_in[19];

    float* preds  = (float*)d_out;
    float* alphas = preds + (size_t)Bv * Tv * Vv;

    k_zero_tail<<<(Bv * Vv + Bv * Pv + 255) / 256, 256>>>(preds, alphas);
    k_mean<<<(Bv * ENCv * 32 + 255) / 256, 256>>>(eo);
    k_init<<<(2 * Bv * Dv * 32 + 255) / 256, 256>>>(ihW, ihb, icW, icb);
    k_encproj<<<dim3(98, 8), 256>>>(eo, encW, encb);

    for (int t = 0; t < NSTEP; t++) {
        k_att<<<Bv, 256>>>(decW, decb, fullW, fullb, alphas, t);
        k_ctx<<<dim3(8, Bv), 256>>>(eo);
        k_xcat<<<Bv, 256>>>(caps, emb, t);
        k_gates<<<dim3(32, KSPLIT), 256>>>(Wih, Whh);
        k_lstm<<<(Bv * Dv + 255) / 256, 256>>>(bih, bhh);
        k_fc<<<157, 256>>>(fcW, fcb, preds, t);
    }
}

// round 2
// speedup vs baseline: 1.9896x; 1.9896x over previous
#include <cuda_runtime.h>
#include <math.h>

#define Bv    64
#define Pv    196
#define ENCv  2048
#define Ev    512
#define Dv    512
#define Av    512
#define Vv    10000
#define Tv    32
#define NSTEP 31
#define G4D   2048          // 4*D
#define KCAT  3072          // E + ENC + D
#define KSPLIT 8
#define KCHUNK 384          // KCAT / KSPLIT

typedef unsigned long long ull;

// ------------------------- scratch (static device globals) -------------------
__device__ float g_enc_proj[Bv * Pv * Av];     // 25.7 MB
__device__ float g_mean[Bv * ENCv];
__device__ float g_h[Bv * Dv];
__device__ float g_c[Bv * Dv];
__device__ float g_dh[Bv * Av];
__device__ float g_e[Bv * Pv];
__device__ float g_xcat[Bv * KCAT];
__device__ float g_gpart[KSPLIT][Bv * G4D];    // 4 MB

// ------------------------------- helpers -------------------------------------
__device__ __forceinline__ ull pk2(float lo, float hi) {
    ull r; asm("mov.b64 %0, {%1, %2};" : "=l"(r) : "f"(lo), "f"(hi)); return r;
}
__device__ __forceinline__ void fma2(ull& d, ull a, ull b) {
    asm("fma.rn.f32x2 %0, %1, %2, %0;" : "+l"(d) : "l"(a), "l"(b));
}
__device__ __forceinline__ float2 up2(ull v) {
    float lo, hi; asm("mov.b64 {%0, %1}, %2;" : "=f"(lo), "=f"(hi) : "l"(v));
    return make_float2(lo, hi);
}
__device__ __forceinline__ float wsum(float v) {
#pragma unroll
    for (int o = 16; o; o >>= 1) v += __shfl_down_sync(0xffffffffu, v, o);
    return v;
}
__device__ __forceinline__ float sigm(float x) { return 1.0f / (1.0f + expf(-x)); }

// --------------------------- zero last timestep -------------------------------
__global__ void k_zero_tail(float* __restrict__ preds, float* __restrict__ alphas) {
    int idx = blockIdx.x * blockDim.x + threadIdx.x;
    if (idx < Bv * Vv) {
        int b = idx / Vv, v = idx % Vv;
        preds[((size_t)b * Tv + (Tv - 1)) * Vv + v] = 0.0f;
    } else {
        int r = idx - Bv * Vv;
        if (r < Bv * Pv) {
            int b = r / Pv, p = r % Pv;
            alphas[((size_t)b * Tv + (Tv - 1)) * Pv + p] = 0.0f;
        }
    }
}

// -------------------------------- mean over P ---------------------------------
__global__ void k_mean(const float* __restrict__ eo) {
    int gw = (blockIdx.x * blockDim.x + threadIdx.x) >> 5;
    int lane = threadIdx.x & 31;
    if (gw >= Bv * ENCv) return;
    const float* row = eo + (size_t)gw * Pv;
    float acc = 0.0f;
    for (int p = lane; p < Pv; p += 32) acc += row[p];
    acc = wsum(acc);
    if (!lane) g_mean[gw] = acc * (1.0f / (float)Pv);
}

// -------------------------------- h0 / c0 -------------------------------------
__global__ void k_init(const float* __restrict__ Wh, const float* __restrict__ bh,
                       const float* __restrict__ Wc, const float* __restrict__ bc) {
    int gw = (blockIdx.x * blockDim.x + threadIdx.x) >> 5;
    int lane = threadIdx.x & 31;
    if (gw >= 2 * Bv * Dv) return;
    int sel = gw >= Bv * Dv;
    int r = gw - sel * Bv * Dv;
    int b = r / Dv, d = r % Dv;
    const float* W = sel ? Wc : Wh;
    const float* mn = g_mean + (size_t)b * ENCv;
    const float* wr = W + (size_t)d * ENCv;
    float acc = 0.0f;
    for (int k = lane; k < ENCv; k += 32) acc += mn[k] * wr[k];
    acc = wsum(acc);
    if (!lane) (sel ? g_c : g_h)[r] = acc + (sel ? bc : bh)[d];
}

// ------------------------------ enc_proj GEMM ---------------------------------
// 128x128 tile, BK=16, 256 threads, 8x8 per thread, ping-pong double buffer.
__global__ __launch_bounds__(256, 2)
void k_encproj(const float* __restrict__ eo,
               const float* __restrict__ W,
               const float* __restrict__ bias) {
    __shared__ float Xs[2][16][128];
    __shared__ float Wsh[2][16][128];
    int m0 = blockIdx.x * 128;      // 98 m-tiles
    int n0 = blockIdx.y * 128;      // 4 n-tiles
    int tid = threadIdx.x;
    int tx = tid & 15, ty = tid >> 4;

    // X loader: xm constant, k = xkb + 2r
    int xm = tid & 127;
    int xkb = tid >> 7;             // 0 or 1
    int m = m0 + xm;
    int b = m / Pv;
    int p = m - b * Pv;
    int xoff = b * (ENCv * Pv) + p;

    // W loader: k = tx, n = ty + 16r
    // global: W[(n0 + ty + 16r) * ENCv + k0 + tx]

    ull acc[4][8];
#pragma unroll
    for (int i = 0; i < 4; i++)
#pragma unroll
        for (int j = 0; j < 8; j++) acc[i][j] = 0ull;

    // prologue: tile k0 = 0 into buffer 0
#pragma unroll
    for (int r = 0; r < 8; r++)
        Xs[0][xkb + 2 * r][xm] = eo[xoff + (xkb + 2 * r) * Pv];
#pragma unroll
    for (int r = 0; r < 8; r++)
        Wsh[0][tx][ty + 16 * r] = W[(size_t)(n0 + ty + 16 * r) * ENCv + tx];
    __syncthreads();

    int buf = 0;
    for (int k0 = 0; k0 < ENCv; k0 += 16) {
        float xr[8], wr[8];
        bool more = (k0 + 16 < ENCv);
        if (more) {
#pragma unroll
            for (int r = 0; r < 8; r++)
                xr[r] = eo[xoff + (k0 + 16 + xkb + 2 * r) * Pv];
#pragma unroll
            for (int r = 0; r < 8; r++)
                wr[r] = W[(size_t)(n0 + ty + 16 * r) * ENCv + k0 + 16 + tx];
        }
#pragma unroll
        for (int k = 0; k < 16; k++) {
            ull a2[4];
#pragma unroll
            for (int i = 0; i < 4; i++)
                a2[i] = *(const ull*)&Xs[buf][k][ty * 8 + 2 * i];
            float4 blo = *(const float4*)&Wsh[buf][k][tx * 8];
            float4 bhi = *(const float4*)&Wsh[buf][k][tx * 8 + 4];
            ull bd[8];
            bd[0] = pk2(blo.x, blo.x); bd[1] = pk2(blo.y, blo.y);
            bd[2] = pk2(blo.z, blo.z); bd[3] = pk2(blo.w, blo.w);
            bd[4] = pk2(bhi.x, bhi.x); bd[5] = pk2(bhi.y, bhi.y);
            bd[6] = pk2(bhi.z, bhi.z); bd[7] = pk2(bhi.w, bhi.w);
#pragma unroll
            for (int j = 0; j < 8; j++)
#pragma unroll
                for (int i = 0; i < 4; i++) fma2(acc[i][j], a2[i], bd[j]);
        }
        if (more) {
#pragma unroll
            for (int r = 0; r < 8; r++) Xs[buf ^ 1][xkb + 2 * r][xm] = xr[r];
#pragma unroll
            for (int r = 0; r < 8; r++) Wsh[buf ^ 1][tx][ty + 16 * r] = wr[r];
        }
        __syncthreads();
        buf ^= 1;
    }

#pragma unroll
    for (int j = 0; j < 8; j++) {
        int n = n0 + tx * 8 + j;
        float bb = bias[n];
#pragma unroll
        for (int i = 0; i < 4; i++) {
            float2 v = up2(acc[i][j]);
            int mm = m0 + ty * 8 + 2 * i;
            g_enc_proj[(size_t)mm * Av + n] = v.x + bb;
            g_enc_proj[(size_t)(mm + 1) * Av + n] = v.y + bb;
        }
    }
}

// --------------------- dh = h @ decW.T + decb  (+ xcat emb/h fill) -------------
__global__ void k_dh(const float* __restrict__ decW, const float* __restrict__ decb,
                     const int* __restrict__ caps, const float* __restrict__ emb, int t) {
    int tid = threadIdx.x;
    // first 64 blocks also fill the emb and h slices of xcat
    if (blockIdx.x < Bv) {
        int b = blockIdx.x;
        int cap = caps[b * Tv + t];
        for (int j = tid; j < Ev + Dv; j += 256) {
            if (j < Ev) g_xcat[b * KCAT + j] = emb[(size_t)cap * Ev + j];
            else        g_xcat[b * KCAT + (Ev + ENCv) + (j - Ev)] = g_h[b * Dv + (j - Ev)];
        }
    }
    int gw = (blockIdx.x * 256 + tid) >> 5;   // 0 .. 32767
    int lane = tid & 31;
    int b = gw >> 9;            // /512
    int a = gw & 511;
    const float* hr = g_h + b * Dv;
    const float* wr = decW + (size_t)a * Dv;
    float acc = 0.0f;
#pragma unroll
    for (int k = lane; k < Dv; k += 32) acc += hr[k] * wr[k];
    acc = wsum(acc);
    if (!lane) g_dh[b * Av + a] = acc + decb[a];
}

// --------------------- e[b,p] = relu(enc_proj + dh) . fullW + fullb ------------
__global__ void k_e(const float* __restrict__ fullW, const float* __restrict__ fullb) {
    int gw = (blockIdx.x * 256 + threadIdx.x) >> 5;   // 0 .. 12543
    int lane = threadIdx.x & 31;
    if (gw >= Bv * Pv) return;
    int b = gw / Pv;
    const float* ep = g_enc_proj + (size_t)gw * Av;
    const float* dh = g_dh + b * Av;
    float acc = 0.0f;
#pragma unroll
    for (int k = lane; k < Av; k += 32) {
        float v = ep[k] + dh[k];
        acc += fmaxf(v, 0.0f) * fullW[k];
    }
    acc = wsum(acc);
    if (!lane) g_e[gw] = acc + fullb[0];
}

// -------------- softmax (redundant per block) + context -> xcat ----------------
// grid (256, B): block handles 8 e-rows (warp each) of one batch element.
__global__ void k_ctx(const float* __restrict__ eo, float* __restrict__ out_alphas, int t) {
    __shared__ float red[256];
    __shared__ float sal[Pv];
    int b = blockIdx.y;
    int tid = threadIdx.x;
    int w = tid >> 5, lane = tid & 31;

    // softmax over P=196 (every block recomputes; cheap, from L2)
    float v = (tid < Pv) ? g_e[b * Pv + tid] : -3.0e38f;
    red[tid] = v; __syncthreads();
    for (int s = 128; s; s >>= 1) {
        if (tid < s) red[tid] = fmaxf(red[tid], red[tid + s]);
        __syncthreads();
    }
    float mx = red[0]; __syncthreads();
    float ex = (tid < Pv) ? expf(v - mx) : 0.0f;
    red[tid] = ex; __syncthreads();
    for (int s = 128; s; s >>= 1) {
        if (tid < s) red[tid] += red[tid + s];
        __syncthreads();
    }
    float inv = 1.0f / red[0];
    if (tid < Pv) {
        float al = ex * inv;
        sal[tid] = al;
        if (blockIdx.x == 0)
            out_alphas[((size_t)b * Tv + t) * Pv + tid] = al;
    }
    __syncthreads();

    // context: one warp per e-row
    int e = blockIdx.x * 8 + w;    // 0 .. 2047
    const float* row = eo + (size_t)b * ENCv * Pv + (size_t)e * Pv;
    float acc = 0.0f;
#pragma unroll
    for (int pp = lane; pp < Pv; pp += 32) acc += sal[pp] * row[pp];
    acc = wsum(acc);
    if (!lane) g_xcat[b * KCAT + Ev + e] = acc;
}

// ------------------------------ gates GEMM (K-split) ---------------------------
__global__ void k_gates(const float* __restrict__ Wih, const float* __restrict__ Whh) {
    __shared__ float Xs[16][68];
    __shared__ float Ws[16][68];
    int n0 = blockIdx.x * 64;        // 32 tiles
    int z = blockIdx.y;              // 8 k-chunks
    int kbase = z * KCHUNK;
    int tid = threadIdx.x;
    int tx = tid & 15, ty = tid >> 4;

    ull acc[2][4];
#pragma unroll
    for (int i = 0; i < 2; i++)
#pragma unroll
        for (int j = 0; j < 4; j++) acc[i][j] = 0ull;

    for (int k0 = 0; k0 < KCHUNK; k0 += 16) {
#pragma unroll
        for (int r = 0; r < 4; r++) {
            int i = tid + 256 * r;
            int kk = i & 15;
            int mm = i >> 4;
            int kg = kbase + k0 + kk;
            Xs[kk][mm] = g_xcat[mm * KCAT + kg];
            int n = n0 + mm;
            Ws[kk][mm] = (kg < Ev + ENCv)
                           ? Wih[(size_t)n * (Ev + ENCv) + kg]
                           : Whh[(size_t)n * Dv + (kg - (Ev + ENCv))];
        }
        __syncthreads();
#pragma unroll
        for (int k = 0; k < 16; k++) {
            ull a2[2];
            a2[0] = *(const ull*)&Xs[k][ty * 4];
            a2[1] = *(const ull*)&Xs[k][ty * 4 + 2];
#pragma unroll
            for (int j = 0; j < 4; j++) {
                float bv = Ws[k][tx * 4 + j];
                ull bd = pk2(bv, bv);
                fma2(acc[0][j], a2[0], bd);
                fma2(acc[1][j], a2[1], bd);
            }
        }
        __syncthreads();
    }
#pragma unroll
    for (int j = 0; j < 4; j++) {
        int n = n0 + tx * 4 + j;
#pragma unroll
        for (int i = 0; i < 2; i++) {
            float2 v = up2(acc[i][j]);
            int mm = ty * 4 + 2 * i;
            g_gpart[z][mm * G4D + n] = v.x;
            g_gpart[z][(mm + 1) * G4D + n] = v.y;
        }
    }
}

// ------------------------------ LSTM pointwise ---------------------------------
__global__ void k_lstm(const float* __restrict__ bih, const float* __restrict__ bhh) {
    int idx = blockIdx.x * blockDim.x + threadIdx.x;
    if (idx >= Bv * Dv) return;
    int b = idx / Dv, d = idx % Dv;
    float gi = bih[d] + bhh[d];
    float gf = bih[Dv + d] + bhh[Dv + d];
    float gg = bih[2 * Dv + d] + bhh[2 * Dv + d];
    float go = bih[3 * Dv + d] + bhh[3 * Dv + d];
    int base = b * G4D + d;
#pragma unroll
    for (int z = 0; z < KSPLIT; z++) {
        gi += g_gpart[z][base];
        gf += g_gpart[z][base + Dv];
        gg += g_gpart[z][base + 2 * Dv];
        go += g_gpart[z][base + 3 * Dv];
    }
    float c = g_c[idx];
    float cn = sigm(gf) * c + sigm(gi) * tanhf(gg);
    float hn = sigm(go) * tanhf(cn);
    g_c[idx] = cn;
    g_h[idx] = hn;
}

// ------------------------------ fc GEMM (preds) ---------------------------------
__global__ void k_fc(const float* __restrict__ Wf, const float* __restrict__ bf,
                     float* __restrict__ preds, int t) {
    __shared__ float Xs[16][68];
    __shared__ float Ws[16][68];
    int n0 = blockIdx.x * 64;     // 157 tiles (bounds-checked)
    int tid = threadIdx.x;
    int tx = tid & 15, ty = tid >> 4;

    ull acc[2][4];
#pragma unroll
    for (int i = 0; i < 2; i++)
#pragma unroll
        for (int j = 0; j < 4; j++) acc[i][j] = 0ull;

    for (int k0 = 0; k0 < Dv; k0 += 16) {
#pragma unroll
        for (int r = 0; r < 4; r++) {
            int i = tid + 256 * r;
            int kk = i & 15;
            int mm = i >> 4;
            Xs[kk][mm] = g_h[mm * Dv + k0 + kk];
            int n = n0 + mm;
            Ws[kk][mm] = (n < Vv) ? Wf[(size_t)n * Dv + k0 + kk] : 0.0f;
        }
        __syncthreads();
#pragma unroll
        for (int k = 0; k < 16; k++) {
            ull a2[2];
            a2[0] = *(const ull*)&Xs[k][ty * 4];
            a2[1] = *(const ull*)&Xs[k][ty * 4 + 2];
#pragma unroll
            for (int j = 0; j < 4; j++) {
                float bv = Ws[k][tx * 4 + j];
                ull bd = pk2(bv, bv);
                fma2(acc[0][j], a2[0], bd);
                fma2(acc[1][j], a2[1], bd);
            }
        }
        __syncthreads();
    }
#pragma unroll
    for (int j = 0; j < 4; j++) {
        int n = n0 + tx * 4 + j;
        if (n >= Vv) continue;
        float bb = bf[n];
#pragma unroll
        for (int i = 0; i < 2; i++) {
            float2 v = up2(acc[i][j]);
            int mm = ty * 4 + 2 * i;
            preds[((size_t)mm * Tv + t) * Vv + n] = v.x + bb;
            preds[((size_t)(mm + 1) * Tv + t) * Vv + n] = v.y + bb;
        }
    }
}

// --------------------------------- launcher ------------------------------------
extern "C" void kernel_launch(void* const* d_in, const int* in_sizes, int n_in,
                              void* d_out, int out_size) {
    const float* eo    = (const float*)d_in[0];
    const int*   caps  = (const int*)d_in[1];
    const float* emb   = (const float*)d_in[3];
    const float* encW  = (const float*)d_in[4];
    const float* encb  = (const float*)d_in[5];
    const float* decW  = (const float*)d_in[6];
    const float* decb  = (const float*)d_in[7];
    const float* fullW = (const float*)d_in[8];
    const float* fullb = (const float*)d_in[9];
    const float* ihW   = (const float*)d_in[10];
    const float* ihb   = (const float*)d_in[11];
    const float* icW   = (const float*)d_in[12];
    const float* icb   = (const float*)d_in[13];
    const float* Wih   = (const float*)d_in[14];
    const float* bih   = (const float*)d_in[15];
    const float* Whh   = (const float*)d_in[16];
    const float* bhh   = (const float*)d_in[17];
    const float* fcW   = (const float*)d_in[18];
    const float* fcb   = (const float*)d_in[19];

    float* preds  = (float*)d_out;
    float* alphas = preds + (size_t)Bv * Tv * Vv;

    k_zero_tail<<<(Bv * Vv + Bv * Pv + 255) / 256, 256>>>(preds, alphas);
    k_mean<<<(Bv * ENCv * 32 + 255) / 256, 256>>>(eo);
    k_init<<<(2 * Bv * Dv * 32 + 255) / 256, 256>>>(ihW, ihb, icW, icb);
    k_encproj<<<dim3(98, 4), 256>>>(eo, encW, encb);

    for (int t = 0; t < NSTEP; t++) {
        k_dh<<<4096, 256>>>(decW, decb, caps, emb, t);
        k_e<<<1568, 256>>>(fullW, fullb);
        k_ctx<<<dim3(256, Bv), 256>>>(eo, alphas, t);
        k_gates<<<dim3(32, KSPLIT), 256>>>(Wih, Whh);
        k_lstm<<<(Bv * Dv + 255) / 256, 256>>>(bih, bhh);
        k_fc<<<157, 256>>>(fcW, fcb, preds, t);
    }
}

// round 4
// speedup vs baseline: 2.0493x; 1.0300x over previous
#include <cuda_runtime.h>
#include <math.h>

#define Bv    64
#define Pv    196
#define ENCv  2048
#define Ev    512
#define Dv    512
#define Av    512
#define Vv    10000
#define Tv    32
#define NSTEP 31
#define G4D   2048          // 4*D
#define KIN   2560          // ENC + D (ctx | h)
#define KIN_W 2560          // Wih row stride (E+ENC)
#define KSPLIT 8
#define KCHUNK 320          // KIN / KSPLIT

typedef unsigned long long ull;

// ------------------------- scratch (static device globals) -------------------
__device__ float g_enc_proj[Bv * Pv * Av];     // 25.7 MB
__device__ float g_mean[Bv * ENCv];
__device__ float g_h[Bv * Dv];
__device__ float g_c[Bv * Dv];
__device__ float g_dh[Bv * Av];
__device__ float g_e[Bv * Pv];
__device__ float g_xin[Bv * KIN];              // [ctx(2048) | h(512)]
__device__ float g_gpart[KSPLIT][Bv * G4D];    // 4 MB
__device__ float g_gemb[NSTEP * Bv * G4D];     // 16.2 MB: emb @ Wih_emb.T per step

// ------------------------------- helpers -------------------------------------
__device__ __forceinline__ ull pk2(float lo, float hi) {
    ull r; asm("mov.b64 %0, {%1, %2};" : "=l"(r) : "f"(lo), "f"(hi)); return r;
}
__device__ __forceinline__ void fma2(ull& d, ull a, ull b) {
    asm("fma.rn.f32x2 %0, %1, %2, %0;" : "+l"(d) : "l"(a), "l"(b));
}
__device__ __forceinline__ float2 up2(ull v) {
    float lo, hi; asm("mov.b64 {%0, %1}, %2;" : "=f"(lo), "=f"(hi) : "l"(v));
    return make_float2(lo, hi);
}
__device__ __forceinline__ float wsum(float v) {
#pragma unroll
    for (int o = 16; o; o >>= 1) v += __shfl_down_sync(0xffffffffu, v, o);
    return v;
}
__device__ __forceinline__ float sigm(float x) { return 1.0f / (1.0f + expf(-x)); }

// --------------------------- zero last timestep -------------------------------
__global__ void k_zero_tail(float* __restrict__ preds, float* __restrict__ alphas) {
    int idx = blockIdx.x * blockDim.x + threadIdx.x;
    if (idx < Bv * Vv) {
        int b = idx / Vv, v = idx % Vv;
        preds[((size_t)b * Tv + (Tv - 1)) * Vv + v] = 0.0f;
    } else {
        int r = idx - Bv * Vv;
        if (r < Bv * Pv) {
            int b = r / Pv, p = r % Pv;
            alphas[((size_t)b * Tv + (Tv - 1)) * Pv + p] = 0.0f;
        }
    }
}

// -------------------------------- mean over P ---------------------------------
__global__ void k_mean(const float* __restrict__ eo) {
    int gw = (blockIdx.x * blockDim.x + threadIdx.x) >> 5;
    int lane = threadIdx.x & 31;
    if (gw >= Bv * ENCv) return;
    const float* row = eo + (size_t)gw * Pv;
    float acc = 0.0f;
    for (int p = lane; p < Pv; p += 32) acc += row[p];
    acc = wsum(acc);
    if (!lane) g_mean[gw] = acc * (1.0f / (float)Pv);
}

// -------------------------------- h0 / c0 -------------------------------------
__global__ void k_init(const float* __restrict__ Wh, const float* __restrict__ bh,
                       const float* __restrict__ Wc, const float* __restrict__ bc) {
    int gw = (blockIdx.x * blockDim.x + threadIdx.x) >> 5;
    int lane = threadIdx.x & 31;
    if (gw >= 2 * Bv * Dv) return;
    int sel = gw >= Bv * Dv;
    int r = gw - sel * Bv * Dv;
    int b = r / Dv, d = r % Dv;
    const float* W = sel ? Wc : Wh;
    const float* mn = g_mean + (size_t)b * ENCv;
    const float* wr = W + (size_t)d * ENCv;
    float acc = 0.0f;
    for (int k = lane; k < ENCv; k += 32) acc += mn[k] * wr[k];
    acc = wsum(acc);
    if (!lane) {
        float v = acc + (sel ? bc : bh)[d];
        if (sel) g_c[r] = v;
        else { g_h[r] = v; g_xin[b * KIN + ENCv + d] = v; }
    }
}

// ------------------------------ enc_proj GEMM ---------------------------------
// 128x128 tile, BK=16, 256 threads, (4+4)x(4+4) micro, double buffered.
__global__ __launch_bounds__(256, 2)
void k_encproj(const float* __restrict__ eo,
               const float* __restrict__ W,
               const float* __restrict__ bias) {
    __shared__ float Xs[2][16][128];
    __shared__ float Wsh[2][16][132];   // padded: 2-way STS conflicts max
    int m0 = blockIdx.x * 128;      // 98 m-tiles
    int n0 = blockIdx.y * 128;      // 4 n-tiles
    int tid = threadIdx.x;
    int tx = tid & 15, ty = tid >> 4;

    // X loader
    int xm = tid & 127;
    int xkb = tid >> 7;             // 0 or 1
    int m_ = m0 + xm;
    int b_ = m_ / Pv;
    int p_ = m_ - b_ * Pv;
    int xoff = b_ * (ENCv * Pv) + p_;

    ull acc[4][8];
#pragma unroll
    for (int i = 0; i < 4; i++)
#pragma unroll
        for (int j = 0; j < 8; j++) acc[i][j] = 0ull;

    // prologue
#pragma unroll
    for (int r = 0; r < 8; r++)
        Xs[0][xkb + 2 * r][xm] = eo[xoff + (xkb + 2 * r) * Pv];
#pragma unroll
    for (int r = 0; r < 8; r++)
        Wsh[0][tx][ty + 16 * r] = W[(size_t)(n0 + ty + 16 * r) * ENCv + tx];
    __syncthreads();

    int buf = 0;
    for (int k0 = 0; k0 < ENCv; k0 += 16) {
        float xr[8], wr[8];
        bool more = (k0 + 16 < ENCv);
        if (more) {
#pragma unroll
            for (int r = 0; r < 8; r++)
                xr[r] = eo[xoff + (k0 + 16 + xkb + 2 * r) * Pv];
#pragma unroll
            for (int r = 0; r < 8; r++)
                wr[r] = W[(size_t)(n0 + ty + 16 * r) * ENCv + k0 + 16 + tx];
        }
#pragma unroll
        for (int k = 0; k < 16; k++) {
            ull a2[4];
            a2[0] = *(const ull*)&Xs[buf][k][ty * 4];
            a2[1] = *(const ull*)&Xs[buf][k][ty * 4 + 2];
            a2[2] = *(const ull*)&Xs[buf][k][64 + ty * 4];
            a2[3] = *(const ull*)&Xs[buf][k][64 + ty * 4 + 2];
            float4 blo = *(const float4*)&Wsh[buf][k][tx * 4];
            float4 bhi = *(const float4*)&Wsh[buf][k][64 + tx * 4];
            ull bd[8];
            bd[0] = pk2(blo.x, blo.x); bd[1] = pk2(blo.y, blo.y);
            bd[2] = pk2(blo.z, blo.z); bd[3] = pk2(blo.w, blo.w);
            bd[4] = pk2(bhi.x, bhi.x); bd[5] = pk2(bhi.y, bhi.y);
            bd[6] = pk2(bhi.z, bhi.z); bd[7] = pk2(bhi.w, bhi.w);
#pragma unroll
            for (int j = 0; j < 8; j++)
#pragma unroll
                for (int i = 0; i < 4; i++) fma2(acc[i][j], a2[i], bd[j]);
        }
        if (more) {
#pragma unroll
            for (int r = 0; r < 8; r++) Xs[buf ^ 1][xkb + 2 * r][xm] = xr[r];
#pragma unroll
            for (int r = 0; r < 8; r++) Wsh[buf ^ 1][tx][ty + 16 * r] = wr[r];
        }
        __syncthreads();
        buf ^= 1;
    }

#pragma unroll
    for (int j = 0; j < 8; j++) {
        int n = n0 + (j < 4 ? tx * 4 + j : 64 + tx * 4 + (j - 4));
        float bb = bias[n];
#pragma unroll
        for (int i = 0; i < 4; i++) {
            float2 v = up2(acc[i][j]);
            int mm = m0 + (i < 2 ? ty * 4 + 2 * i : 64 + ty * 4 + 2 * (i - 2));
            g_enc_proj[(size_t)mm * Av + n] = v.x + bb;
            g_enc_proj[(size_t)(mm + 1) * Av + n] = v.y + bb;
        }
    }
}

// ------------------ precompute emb @ Wih_emb.T for all steps -------------------
// out g_gemb[(t*64+b)*2048 + n]; M = 31*64 = 1984, N = 2048, K = 512.
__global__ void k_embW(const int* __restrict__ caps, const float* __restrict__ emb,
                       const float* __restrict__ Wih) {
    __shared__ float Xs[2][16][68];
    __shared__ float Ws[2][16][68];
    int n0 = blockIdx.x * 64;     // 32
    int m0 = blockIdx.y * 64;     // 31
    int tid = threadIdx.x;
    int tx = tid & 15, ty = tid >> 4;

    // loader rows
    int caprow[4];
#pragma unroll
    for (int r = 0; r < 4; r++) {
        int mm = ty + 16 * r;
        int m = m0 + mm;
        int b = m & 63, t = m >> 6;
        caprow[r] = caps[b * Tv + t];
    }

    ull acc[2][4];
#pragma unroll
    for (int i = 0; i < 2; i++)
#pragma unroll
        for (int j = 0; j < 4; j++) acc[i][j] = 0ull;

#pragma unroll
    for (int r = 0; r < 4; r++) {
        Xs[0][tx][ty + 16 * r] = emb[(size_t)caprow[r] * Ev + tx];
        Ws[0][tx][ty + 16 * r] = Wih[(size_t)(n0 + ty + 16 * r) * KIN_W + tx];
    }
    __syncthreads();
    int buf = 0;
    for (int k0 = 0; k0 < Ev; k0 += 16) {
        float xr[4], wr[4];
        bool more = (k0 + 16 < Ev);
        if (more) {
#pragma unroll
            for (int r = 0; r < 4; r++) {
                xr[r] = emb[(size_t)caprow[r] * Ev + k0 + 16 + tx];
                wr[r] = Wih[(size_t)(n0 + ty + 16 * r) * KIN_W + k0 + 16 + tx];
            }
        }
#pragma unroll
        for (int k = 0; k < 16; k++) {
            ull a0 = *(const ull*)&Xs[buf][k][ty * 4];
            ull a1 = *(const ull*)&Xs[buf][k][ty * 4 + 2];
            float4 bq = *(const float4*)&Ws[buf][k][tx * 4];
            ull bd0 = pk2(bq.x, bq.x), bd1 = pk2(bq.y, bq.y);
            ull bd2 = pk2(bq.z, bq.z), bd3 = pk2(bq.w, bq.w);
            fma2(acc[0][0], a0, bd0); fma2(acc[1][0], a1, bd0);
            fma2(acc[0][1], a0, bd1); fma2(acc[1][1], a1, bd1);
            fma2(acc[0][2], a0, bd2); fma2(acc[1][2], a1, bd2);
            fma2(acc[0][3], a0, bd3); fma2(acc[1][3], a1, bd3);
        }
        if (more) {
#pragma unroll
            for (int r = 0; r < 4; r++) {
                Xs[buf ^ 1][tx][ty + 16 * r] = xr[r];
                Ws[buf ^ 1][tx][ty + 16 * r] = wr[r];
            }
        }
        __syncthreads();
        buf ^= 1;
    }
#pragma unroll
    for (int j = 0; j < 4; j++) {
        int n = n0 + tx * 4 + j;
#pragma unroll
        for (int i = 0; i < 2; i++) {
            float2 v = up2(acc[i][j]);
            int m = m0 + ty * 4 + 2 * i;
            g_gemb[(size_t)m * G4D + n] = v.x;
            g_gemb[(size_t)(m + 1) * G4D + n] = v.y;
        }
    }
}

// --------------------- dh = h @ decW.T + decb  (tiled GEMM) --------------------
__global__ void k_dh(const float* __restrict__ decW, const float* __restrict__ decb) {
    __shared__ float Xs[2][16][68];
    __shared__ float Ws[2][16][68];
    int n0 = blockIdx.x * 64;     // 8 tiles
    int tid = threadIdx.x;
    int tx = tid & 15, ty = tid >> 4;

    ull acc[2][4];
#pragma unroll
    for (int i = 0; i < 2; i++)
#pragma unroll
        for (int j = 0; j < 4; j++) acc[i][j] = 0ull;

#pragma unroll
    for (int r = 0; r < 4; r++) {
        int mm = ty + 16 * r;
        Xs[0][tx][mm] = g_h[mm * Dv + tx];
        Ws[0][tx][mm] = decW[(size_t)(n0 + mm) * Dv + tx];
    }
    __syncthreads();
    int buf = 0;
    for (int k0 = 0; k0 < Dv; k0 += 16) {
        float xr[4], wr[4];
        bool more = (k0 + 16 < Dv);
        if (more) {
#pragma unroll
            for (int r = 0; r < 4; r++) {
                int mm = ty + 16 * r;
                xr[r] = g_h[mm * Dv + k0 + 16 + tx];
                wr[r] = decW[(size_t)(n0 + mm) * Dv + k0 + 16 + tx];
            }
        }
#pragma unroll
        for (int k = 0; k < 16; k++) {
            ull a0 = *(const ull*)&Xs[buf][k][ty * 4];
            ull a1 = *(const ull*)&Xs[buf][k][ty * 4 + 2];
            float4 bq = *(const float4*)&Ws[buf][k][tx * 4];
            ull bd0 = pk2(bq.x, bq.x), bd1 = pk2(bq.y, bq.y);
            ull bd2 = pk2(bq.z, bq.z), bd3 = pk2(bq.w, bq.w);
            fma2(acc[0][0], a0, bd0); fma2(acc[1][0], a1, bd0);
            fma2(acc[0][1], a0, bd1); fma2(acc[1][1], a1, bd1);
            fma2(acc[0][2], a0, bd2); fma2(acc[1][2], a1, bd2);
            fma2(acc[0][3], a0, bd3); fma2(acc[1][3], a1, bd3);
        }
        if (more) {
#pragma unroll
            for (int r = 0; r < 4; r++) {
                int mm = ty + 16 * r;
                Xs[buf ^ 1][tx][mm] = xr[r];
                Ws[buf ^ 1][tx][mm] = wr[r];
            }
        }
        __syncthreads();
        buf ^= 1;
    }
#pragma unroll
    for (int j = 0; j < 4; j++) {
        int n = n0 + tx * 4 + j;
        float bb = decb[n];
#pragma unroll
        for (int i = 0; i < 2; i++) {
            float2 v = up2(acc[i][j]);
            int m = ty * 4 + 2 * i;
            g_dh[m * Av + n] = v.x + bb;
            g_dh[(m + 1) * Av + n] = v.y + bb;
        }
    }
}

// --------------------- e[b,p] = relu(enc_proj + dh) . fullW + fullb ------------
__global__ void k_e(const float* __restrict__ fullW, const float* __restrict__ fullb) {
    int gw = (blockIdx.x * 256 + threadIdx.x) >> 5;   // 0 .. 12543
    int lane = threadIdx.x & 31;
    if (gw >= Bv * Pv) return;
    int b = gw / Pv;
    const float* ep = g_enc_proj + (size_t)gw * Av;
    const float* dh = g_dh + b * Av;
    float acc = 0.0f;
#pragma unroll
    for (int k = lane; k < Av; k += 32) {
        float v = ep[k] + dh[k];
        acc += fmaxf(v, 0.0f) * fullW[k];
    }
    acc = wsum(acc);
    if (!lane) g_e[gw] = acc + fullb[0];
}

// -------------- softmax (redundant per block) + context -> xin -----------------
__global__ void k_ctx(const float* __restrict__ eo, float* __restrict__ out_alphas, int t) {
    __shared__ float red[256];
    __shared__ float sal[Pv];
    int b = blockIdx.y;
    int tid = threadIdx.x;
    int w = tid >> 5, lane = tid & 31;

    float v = (tid < Pv) ? g_e[b * Pv + tid] : -3.0e38f;
    red[tid] = v; __syncthreads();
    for (int s = 128; s; s >>= 1) {
        if (tid < s) red[tid] = fmaxf(red[tid], red[tid + s]);
        __syncthreads();
    }
    float mx = red[0]; __syncthreads();
    float ex = (tid < Pv) ? expf(v - mx) : 0.0f;
    red[tid] = ex; __syncthreads();
    for (int s = 128; s; s >>= 1) {
        if (tid < s) red[tid] += red[tid + s];
        __syncthreads();
    }
    float inv = 1.0f / red[0];
    if (tid < Pv) {
        float al = ex * inv;
        sal[tid] = al;
        if (blockIdx.x == 0)
            out_alphas[((size_t)b * Tv + t) * Pv + tid] = al;
    }
    __syncthreads();

    int e = blockIdx.x * 8 + w;    // 0 .. 2047
    const float* row = eo + (size_t)b * ENCv * Pv + (size_t)e * Pv;
    float acc = 0.0f;
#pragma unroll
    for (int pp = lane; pp < Pv; pp += 32) acc += sal[pp] * row[pp];
    acc = wsum(acc);
    if (!lane) g_xin[b * KIN + e] = acc;
}

// ------------------------------ gates GEMM (K-split) ---------------------------
// partial[z][b,n] = sum over k-chunk of xin[b,k] * W(n,k); W = [Wih_ctx | Whh]
__global__ void k_gates(const float* __restrict__ Wih, const float* __restrict__ Whh) {
    __shared__ float Xs[2][16][68];
    __shared__ float Ws[2][16][68];
    int n0 = blockIdx.x * 64;        // 32 tiles
    int z = blockIdx.y;              // 8 chunks
    int kbase = z * KCHUNK;
    int tid = threadIdx.x;
    int tx = tid & 15, ty = tid >> 4;

    ull acc[2][4];
#pragma unroll
    for (int i = 0; i < 2; i++)
#pragma unroll
        for (int j = 0; j < 4; j++) acc[i][j] = 0ull;

#pragma unroll
    for (int r = 0; r < 4; r++) {
        int mm = ty + 16 * r;
        int kg = kbase + tx;
        Xs[0][tx][mm] = g_xin[mm * KIN + kg];
        int n = n0 + mm;
        Ws[0][tx][mm] = (kg < ENCv) ? Wih[(size_t)n * KIN_W + Ev + kg]
                                    : Whh[(size_t)n * Dv + (kg - ENCv)];
    }
    __syncthreads();
    int buf = 0;
    for (int k0 = 0; k0 < KCHUNK; k0 += 16) {
        float xr[4], wr[4];
        bool more = (k0 + 16 < KCHUNK);
        if (more) {
            int kg = kbase + k0 + 16 + tx;
#pragma unroll
            for (int r = 0; r < 4; r++) {
                int mm = ty + 16 * r;
                xr[r] = g_xin[mm * KIN + kg];
                int n = n0 + mm;
                wr[r] = (kg < ENCv) ? Wih[(size_t)n * KIN_W + Ev + kg]
                                    : Whh[(size_t)n * Dv + (kg - ENCv)];
            }
        }
#pragma unroll
        for (int k = 0; k < 16; k++) {
            ull a0 = *(const ull*)&Xs[buf][k][ty * 4];
            ull a1 = *(const ull*)&Xs[buf][k][ty * 4 + 2];
            float4 bq = *(const float4*)&Ws[buf][k][tx * 4];
            ull bd0 = pk2(bq.x, bq.x), bd1 = pk2(bq.y, bq.y);
            ull bd2 = pk2(bq.z, bq.z), bd3 = pk2(bq.w, bq.w);
            fma2(acc[0][0], a0, bd0); fma2(acc[1][0], a1, bd0);
            fma2(acc[0][1], a0, bd1); fma2(acc[1][1], a1, bd1);
            fma2(acc[0][2], a0, bd2); fma2(acc[1][2], a1, bd2);
            fma2(acc[0][3], a0, bd3); fma2(acc[1][3], a1, bd3);
        }
        if (more) {
#pragma unroll
            for (int r = 0; r < 4; r++) {
                int mm = ty + 16 * r;
                Xs[buf ^ 1][tx][mm] = xr[r];
                Ws[buf ^ 1][tx][mm] = wr[r];
            }
        }
        __syncthreads();
        buf ^= 1;
    }
#pragma unroll
    for (int j = 0; j < 4; j++) {
        int n = n0 + tx * 4 + j;
#pragma unroll
        for (int i = 0; i < 2; i++) {
            float2 v = up2(acc[i][j]);
            int m = ty * 4 + 2 * i;
            g_gpart[z][m * G4D + n] = v.x;
            g_gpart[z][(m + 1) * G4D + n] = v.y;
        }
    }
}

// ------------------------------ LSTM pointwise ---------------------------------
__global__ void k_lstm(const float* __restrict__ bih, const float* __restrict__ bhh, int t) {
    int idx = blockIdx.x * blockDim.x + threadIdx.x;
    if (idx >= Bv * Dv) return;
    int b = idx / Dv, d = idx % Dv;
    const float* ge = g_gemb + ((size_t)t * Bv + b) * G4D;
    float gi = bih[d] + bhh[d] + ge[d];
    float gf = bih[Dv + d] + bhh[Dv + d] + ge[Dv + d];
    float gg = bih[2 * Dv + d] + bhh[2 * Dv + d] + ge[2 * Dv + d];
    float go = bih[3 * Dv + d] + bhh[3 * Dv + d] + ge[3 * Dv + d];
    int base = b * G4D + d;
#pragma unroll
    for (int z = 0; z < KSPLIT; z++) {
        gi += g_gpart[z][base];
        gf += g_gpart[z][base + Dv];
        gg += g_gpart[z][base + 2 * Dv];
        go += g_gpart[z][base + 3 * Dv];
    }
    float c = g_c[idx];
    float cn = sigm(gf) * c + sigm(gi) * tanhf(gg);
    float hn = sigm(go) * tanhf(cn);
    g_c[idx] = cn;
    g_h[idx] = hn;
    g_xin[b * KIN + ENCv + d] = hn;
}

// ------------------------------ fc GEMM (preds) ---------------------------------
__global__ void k_fc(const float* __restrict__ Wf, const float* __restrict__ bf,
                     float* __restrict__ preds, int t) {
    __shared__ float Xs[2][16][68];
    __shared__ float Ws[2][16][68];
    int n0 = blockIdx.x * 64;     // 157 tiles
    int tid = threadIdx.x;
    int tx = tid & 15, ty = tid >> 4;

    ull acc[2][4];
#pragma unroll
    for (int i = 0; i < 2; i++)
#pragma unroll
        for (int j = 0; j < 4; j++) acc[i][j] = 0ull;

#pragma unroll
    for (int r = 0; r < 4; r++) {
        int mm = ty + 16 * r;
        Xs[0][tx][mm] = g_h[mm * Dv + tx];
        int n = n0 + mm;
        Ws[0][tx][mm] = (n < Vv) ? Wf[(size_t)n * Dv + tx] : 0.0f;
    }
    __syncthreads();
    int buf = 0;
    for (int k0 = 0; k0 < Dv; k0 += 16) {
        float xr[4], wr[4];
        bool more = (k0 + 16 < Dv);
        if (more) {
#pragma unroll
            for (int r = 0; r < 4; r++) {
                int mm = ty + 16 * r;
                xr[r] = g_h[mm * Dv + k0 + 16 + tx];
                int n = n0 + mm;
                wr[r] = (n < Vv) ? Wf[(size_t)n * Dv + k0 + 16 + tx] : 0.0f;
            }
        }
#pragma unroll
        for (int k = 0; k < 16; k++) {
            ull a0 = *(const ull*)&Xs[buf][k][ty * 4];
            ull a1 = *(const ull*)&Xs[buf][k][ty * 4 + 2];
            float4 bq = *(const float4*)&Ws[buf][k][tx * 4];
            ull bd0 = pk2(bq.x, bq.x), bd1 = pk2(bq.y, bq.y);
            ull bd2 = pk2(bq.z, bq.z), bd3 = pk2(bq.w, bq.w);
            fma2(acc[0][0], a0, bd0); fma2(acc[1][0], a1, bd0);
            fma2(acc[0][1], a0, bd1); fma2(acc[1][1], a1, bd1);
            fma2(acc[0][2], a0, bd2); fma2(acc[1][2], a1, bd2);
            fma2(acc[0][3], a0, bd3); fma2(acc[1][3], a1, bd3);
        }
        if (more) {
#pragma unroll
            for (int r = 0; r < 4; r++) {
                int mm = ty + 16 * r;
                Xs[buf ^ 1][tx][mm] = xr[r];
                Ws[buf ^ 1][tx][mm] = wr[r];
            }
        }
        __syncthreads();
        buf ^= 1;
    }
#pragma unroll
    for (int j = 0; j < 4; j++) {
        int n = n0 + tx * 4 + j;
        if (n >= Vv) continue;
        float bb = bf[n];
#pragma unroll
        for (int i = 0; i < 2; i++) {
            float2 v = up2(acc[i][j]);
            int m = ty * 4 + 2 * i;
            preds[((size_t)m * Tv + t) * Vv + n] = v.x + bb;
            preds[((size_t)(m + 1) * Tv + t) * Vv + n] = v.y + bb;
        }
    }
}

// --------------------------------- launcher ------------------------------------
extern "C" void kernel_launch(void* const* d_in, const int* in_sizes, int n_in,
                              void* d_out, int out_size) {
    const float* eo    = (const float*)d_in[0];
    const int*   caps  = (const int*)d_in[1];
    const float* emb   = (const float*)d_in[3];
    const float* encW  = (const float*)d_in[4];
    const float* encb  = (const float*)d_in[5];
    const float* decW  = (const float*)d_in[6];
    const float* decb  = (const float*)d_in[7];
    const float* fullW = (const float*)d_in[8];
    const float* fullb = (const float*)d_in[9];
    const float* ihW   = (const float*)d_in[10];
    const float* ihb   = (const float*)d_in[11];
    const float* icW   = (const float*)d_in[12];
    const float* icb   = (const float*)d_in[13];
    const float* Wih   = (const float*)d_in[14];
    const float* bih   = (const float*)d_in[15];
    const float* Whh   = (const float*)d_in[16];
    const float* bhh   = (const float*)d_in[17];
    const float* fcW   = (const float*)d_in[18];
    const float* fcb   = (const float*)d_in[19];

    float* preds  = (float*)d_out;
    float* alphas = preds + (size_t)Bv * Tv * Vv;

    k_zero_tail<<<(Bv * Vv + Bv * Pv + 255) / 256, 256>>>(preds, alphas);
    k_mean<<<(Bv * ENCv * 32 + 255) / 256, 256>>>(eo);
    k_init<<<(2 * Bv * Dv * 32 + 255) / 256, 256>>>(ihW, ihb, icW, icb);
    k_embW<<<dim3(32, 31), 256>>>(caps, emb, Wih);
    k_encproj<<<dim3(98, 4), 256>>>(eo, encW, encb);

    for (int t = 0; t < NSTEP; t++) {
        k_dh<<<8, 256>>>(decW, decb);
        k_e<<<1568, 256>>>(fullW, fullb);
        k_ctx<<<dim3(256, Bv), 256>>>(eo, alphas, t);
        k_gates<<<dim3(32, KSPLIT), 256>>>(Wih, Whh);
        k_lstm<<<(Bv * Dv + 255) / 256, 256>>>(bih, bhh, t);
        k_fc<<<157, 256>>>(fcW, fcb, preds, t);
    }
}

// round 6
// speedup vs baseline: 2.3096x; 1.1270x over previous
#include <cuda_runtime.h>
#include <cuda_fp16.h>
#include <math.h>

#define Bv    64
#define Pv    196
#define ENCv  2048
#define Ev    512
#define Dv    512
#define Av    512
#define Vv    10000
#define Tv    32
#define NSTEP 31
#define G4D   2048          // 4*D
#define KIN   2560          // ENC + D (ctx | h)
#define KIN_W 2560          // Wih row stride (E+ENC)
#define KSPLIT 8
#define KCHUNK 320          // KIN / KSPLIT
#define DHZ   4             // dh K-split
#define DHCH  128           // Dv / DHZ

typedef unsigned long long ull;

// ------------------------- scratch (static device globals) -------------------
__device__ float g_enc_proj[Bv * Pv * Av];     // 25.7 MB
__device__ __half g_eo16[Bv * ENCv * Pv];      // 51.4 MB fp16 copy of encoder_out
__device__ float g_mean[Bv * ENCv];
__device__ float g_h[Bv * Dv];
__device__ float g_c[Bv * Dv];
__device__ float g_dhp[DHZ][Bv * Av];
__device__ float g_e[Bv * Pv];
__device__ float g_xin[Bv * KIN];              // [ctx(2048) | h(512)]
__device__ float g_gpart[KSPLIT][Bv * G4D];    // 4 MB
__device__ float g_gemb[NSTEP * Bv * G4D];     // 16.2 MB

// ------------------------------- helpers -------------------------------------
__device__ __forceinline__ ull pk2(float lo, float hi) {
    ull r; asm("mov.b64 %0, {%1, %2};" : "=l"(r) : "f"(lo), "f"(hi)); return r;
}
__device__ __forceinline__ void fma2(ull& d, ull a, ull b) {
    asm("fma.rn.f32x2 %0, %1, %2, %0;" : "+l"(d) : "l"(a), "l"(b));
}
__device__ __forceinline__ float2 up2(ull v) {
    float lo, hi; asm("mov.b64 {%0, %1}, %2;" : "=f"(lo), "=f"(hi) : "l"(v));
    return make_float2(lo, hi);
}
__device__ __forceinline__ float wsum(float v) {
#pragma unroll
    for (int o = 16; o; o >>= 1) v += __shfl_down_sync(0xffffffffu, v, o);
    return v;
}
__device__ __forceinline__ float sigm(float x) { return 1.0f / (1.0f + expf(-x)); }

// --------------------------- zero last timestep -------------------------------
__global__ void k_zero_tail(float* __restrict__ preds, float* __restrict__ alphas) {
    int idx = blockIdx.x * blockDim.x + threadIdx.x;
    if (idx < Bv * Vv) {
        int b = idx / Vv, v = idx % Vv;
        preds[((size_t)b * Tv + (Tv - 1)) * Vv + v] = 0.0f;
    } else {
        int r = idx - Bv * Vv;
        if (r < Bv * Pv) {
            int b = r / Pv, p = r % Pv;
            alphas[((size_t)b * Tv + (Tv - 1)) * Pv + p] = 0.0f;
        }
    }
}

// ----------------------- convert eo to fp16 (one time) -------------------------
__global__ void k_cvt(const float* __restrict__ eo) {
    int i = blockIdx.x * blockDim.x + threadIdx.x;   // float4 index
    const int N4 = Bv * ENCv * Pv / 4;               // 6.42M
    if (i >= N4) return;
    float4 v = ((const float4*)eo)[i];
    __half2* out = (__half2*)g_eo16;
    out[i * 2]     = __floats2half2_rn(v.x, v.y);
    out[i * 2 + 1] = __floats2half2_rn(v.z, v.w);
}

// -------------------------------- mean over P ---------------------------------
__global__ void k_mean(const float* __restrict__ eo) {
    int gw = (blockIdx.x * blockDim.x + threadIdx.x) >> 5;
    int lane = threadIdx.x & 31;
    if (gw >= Bv * ENCv) return;
    const float* row = eo + (size_t)gw * Pv;
    float acc = 0.0f;
    for (int p = lane; p < Pv; p += 32) acc += row[p];
    acc = wsum(acc);
    if (!lane) g_mean[gw] = acc * (1.0f / (float)Pv);
}

// -------------------------------- h0 / c0 -------------------------------------
__global__ void k_init(const float* __restrict__ Wh, const float* __restrict__ bh,
                       const float* __restrict__ Wc, const float* __restrict__ bc) {
    int gw = (blockIdx.x * blockDim.x + threadIdx.x) >> 5;
    int lane = threadIdx.x & 31;
    if (gw >= 2 * Bv * Dv) return;
    int sel = gw >= Bv * Dv;
    int r = gw - sel * Bv * Dv;
    int b = r / Dv, d = r % Dv;
    const float* W = sel ? Wc : Wh;
    const float* mn = g_mean + (size_t)b * ENCv;
    const float* wr = W + (size_t)d * ENCv;
    float acc = 0.0f;
    for (int k = lane; k < ENCv; k += 32) acc += mn[k] * wr[k];
    acc = wsum(acc);
    if (!lane) {
        float v = acc + (sel ? bc : bh)[d];
        if (sel) g_c[r] = v;
        else { g_h[r] = v; g_xin[b * KIN + ENCv + d] = v; }
    }
}

// ------------------------------ enc_proj GEMM ---------------------------------
__global__ __launch_bounds__(256, 2)
void k_encproj(const float* __restrict__ eo,
               const float* __restrict__ W,
               const float* __restrict__ bias) {
    __shared__ float Xs[2][16][128];
    __shared__ float Wsh[2][16][132];
    int m0 = blockIdx.x * 128;
    int n0 = blockIdx.y * 128;
    int tid = threadIdx.x;
    int tx = tid & 15, ty = tid >> 4;

    int xm = tid & 127;
    int xkb = tid >> 7;
    int m_ = m0 + xm;
    int b_ = m_ / Pv;
    int p_ = m_ - b_ * Pv;
    int xoff = b_ * (ENCv * Pv) + p_;

    ull acc[4][8];
#pragma unroll
    for (int i = 0; i < 4; i++)
#pragma unroll
        for (int j = 0; j < 8; j++) acc[i][j] = 0ull;

#pragma unroll
    for (int r = 0; r < 8; r++)
        Xs[0][xkb + 2 * r][xm] = eo[xoff + (xkb + 2 * r) * Pv];
#pragma unroll
    for (int r = 0; r < 8; r++)
        Wsh[0][tx][ty + 16 * r] = W[(size_t)(n0 + ty + 16 * r) * ENCv + tx];
    __syncthreads();

    int buf = 0;
    for (int k0 = 0; k0 < ENCv; k0 += 16) {
        float xr[8], wr[8];
        bool more = (k0 + 16 < ENCv);
        if (more) {
#pragma unroll
            for (int r = 0; r < 8; r++)
                xr[r] = eo[xoff + (k0 + 16 + xkb + 2 * r) * Pv];
#pragma unroll
            for (int r = 0; r < 8; r++)
                wr[r] = W[(size_t)(n0 + ty + 16 * r) * ENCv + k0 + 16 + tx];
        }
#pragma unroll
        for (int k = 0; k < 16; k++) {
            ull a2[4];
            a2[0] = *(const ull*)&Xs[buf][k][ty * 4];
            a2[1] = *(const ull*)&Xs[buf][k][ty * 4 + 2];
            a2[2] = *(const ull*)&Xs[buf][k][64 + ty * 4];
            a2[3] = *(const ull*)&Xs[buf][k][64 + ty * 4 + 2];
            float4 blo = *(const float4*)&Wsh[buf][k][tx * 4];
            float4 bhi = *(const float4*)&Wsh[buf][k][64 + tx * 4];
            ull bd[8];
            bd[0] = pk2(blo.x, blo.x); bd[1] = pk2(blo.y, blo.y);
            bd[2] = pk2(blo.z, blo.z); bd[3] = pk2(blo.w, blo.w);
            bd[4] = pk2(bhi.x, bhi.x); bd[5] = pk2(bhi.y, bhi.y);
            bd[6] = pk2(bhi.z, bhi.z); bd[7] = pk2(bhi.w, bhi.w);
#pragma unroll
            for (int j = 0; j < 8; j++)
#pragma unroll
                for (int i = 0; i < 4; i++) fma2(acc[i][j], a2[i], bd[j]);
        }
        if (more) {
#pragma unroll
            for (int r = 0; r < 8; r++) Xs[buf ^ 1][xkb + 2 * r][xm] = xr[r];
#pragma unroll
            for (int r = 0; r < 8; r++) Wsh[buf ^ 1][tx][ty + 16 * r] = wr[r];
        }
        __syncthreads();
        buf ^= 1;
    }

#pragma unroll
    for (int j = 0; j < 8; j++) {
        int n = n0 + (j < 4 ? tx * 4 + j : 64 + tx * 4 + (j - 4));
        float bb = bias[n];
#pragma unroll
        for (int i = 0; i < 4; i++) {
            float2 v = up2(acc[i][j]);
            int mm = m0 + (i < 2 ? ty * 4 + 2 * i : 64 + ty * 4 + 2 * (i - 2));
            g_enc_proj[(size_t)mm * Av + n] = v.x + bb;
            g_enc_proj[(size_t)(mm + 1) * Av + n] = v.y + bb;
        }
    }
}

// ------------------ precompute emb @ Wih_emb.T for all steps -------------------
__global__ void k_embW(const int* __restrict__ caps, const float* __restrict__ emb,
                       const float* __restrict__ Wih) {
    __shared__ float Xs[2][16][68];
    __shared__ float Ws[2][16][68];
    int n0 = blockIdx.x * 64;
    int m0 = blockIdx.y * 64;
    int tid = threadIdx.x;
    int tx = tid & 15, ty = tid >> 4;

    int caprow[4];
#pragma unroll
    for (int r = 0; r < 4; r++) {
        int mm = ty + 16 * r;
        int m = m0 + mm;
        int b = m & 63, t = m >> 6;
        caprow[r] = caps[b * Tv + t];
    }

    ull acc[2][4];
#pragma unroll
    for (int i = 0; i < 2; i++)
#pragma unroll
        for (int j = 0; j < 4; j++) acc[i][j] = 0ull;

#pragma unroll
    for (int r = 0; r < 4; r++) {
        Xs[0][tx][ty + 16 * r] = emb[(size_t)caprow[r] * Ev + tx];
        Ws[0][tx][ty + 16 * r] = Wih[(size_t)(n0 + ty + 16 * r) * KIN_W + tx];
    }
    __syncthreads();
    int buf = 0;
    for (int k0 = 0; k0 < Ev; k0 += 16) {
        float xr[4], wr[4];
        bool more = (k0 + 16 < Ev);
        if (more) {
#pragma unroll
            for (int r = 0; r < 4; r++) {
                xr[r] = emb[(size_t)caprow[r] * Ev + k0 + 16 + tx];
                wr[r] = Wih[(size_t)(n0 + ty + 16 * r) * KIN_W + k0 + 16 + tx];
            }
        }
#pragma unroll
        for (int k = 0; k < 16; k++) {
            ull a0 = *(const ull*)&Xs[buf][k][ty * 4];
            ull a1 = *(const ull*)&Xs[buf][k][ty * 4 + 2];
            float4 bq = *(const float4*)&Ws[buf][k][tx * 4];
            ull bd0 = pk2(bq.x, bq.x), bd1 = pk2(bq.y, bq.y);
            ull bd2 = pk2(bq.z, bq.z), bd3 = pk2(bq.w, bq.w);
            fma2(acc[0][0], a0, bd0); fma2(acc[1][0], a1, bd0);
            fma2(acc[0][1], a0, bd1); fma2(acc[1][1], a1, bd1);
            fma2(acc[0][2], a0, bd2); fma2(acc[1][2], a1, bd2);
            fma2(acc[0][3], a0, bd3); fma2(acc[1][3], a1, bd3);
        }
        if (more) {
#pragma unroll
            for (int r = 0; r < 4; r++) {
                Xs[buf ^ 1][tx][ty + 16 * r] = xr[r];
                Ws[buf ^ 1][tx][ty + 16 * r] = wr[r];
            }
        }
        __syncthreads();
        buf ^= 1;
    }
#pragma unroll
    for (int j = 0; j < 4; j++) {
        int n = n0 + tx * 4 + j;
#pragma unroll
        for (int i = 0; i < 2; i++) {
            float2 v = up2(acc[i][j]);
            int m = m0 + ty * 4 + 2 * i;
            g_gemb[(size_t)m * G4D + n] = v.x;
            g_gemb[(size_t)(m + 1) * G4D + n] = v.y;
        }
    }
}

// ------------------ dh partials: K-split 4, grid (8, 4) ------------------------
__global__ void k_dh(const float* __restrict__ decW, const float* __restrict__ decb) {
    __shared__ float Xs[2][16][68];
    __shared__ float Ws[2][16][68];
    int n0 = blockIdx.x * 64;
    int z = blockIdx.y;
    int kbase = z * DHCH;
    int tid = threadIdx.x;
    int tx = tid & 15, ty = tid >> 4;

    ull acc[2][4];
#pragma unroll
    for (int i = 0; i < 2; i++)
#pragma unroll
        for (int j = 0; j < 4; j++) acc[i][j] = 0ull;

#pragma unroll
    for (int r = 0; r < 4; r++) {
        int mm = ty + 16 * r;
        Xs[0][tx][mm] = g_h[mm * Dv + kbase + tx];
        Ws[0][tx][mm] = decW[(size_t)(n0 + mm) * Dv + kbase + tx];
    }
    __syncthreads();
    int buf = 0;
    for (int k0 = 0; k0 < DHCH; k0 += 16) {
        float xr[4], wr[4];
        bool more = (k0 + 16 < DHCH);
        if (more) {
#pragma unroll
            for (int r = 0; r < 4; r++) {
                int mm = ty + 16 * r;
                xr[r] = g_h[mm * Dv + kbase + k0 + 16 + tx];
                wr[r] = decW[(size_t)(n0 + mm) * Dv + kbase + k0 + 16 + tx];
            }
        }
#pragma unroll
        for (int k = 0; k < 16; k++) {
            ull a0 = *(const ull*)&Xs[buf][k][ty * 4];
            ull a1 = *(const ull*)&Xs[buf][k][ty * 4 + 2];
            float4 bq = *(const float4*)&Ws[buf][k][tx * 4];
            ull bd0 = pk2(bq.x, bq.x), bd1 = pk2(bq.y, bq.y);
            ull bd2 = pk2(bq.z, bq.z), bd3 = pk2(bq.w, bq.w);
            fma2(acc[0][0], a0, bd0); fma2(acc[1][0], a1, bd0);
            fma2(acc[0][1], a0, bd1); fma2(acc[1][1], a1, bd1);
            fma2(acc[0][2], a0, bd2); fma2(acc[1][2], a1, bd2);
            fma2(acc[0][3], a0, bd3); fma2(acc[1][3], a1, bd3);
        }
        if (more) {
#pragma unroll
            for (int r = 0; r < 4; r++) {
                int mm = ty + 16 * r;
                Xs[buf ^ 1][tx][mm] = xr[r];
                Ws[buf ^ 1][tx][mm] = wr[r];
            }
        }
        __syncthreads();
        buf ^= 1;
    }
#pragma unroll
    for (int j = 0; j < 4; j++) {
        int n = n0 + tx * 4 + j;
        float bb = (z == 0) ? decb[n] : 0.0f;
#pragma unroll
        for (int i = 0; i < 2; i++) {
            float2 v = up2(acc[i][j]);
            int m = ty * 4 + 2 * i;
            g_dhp[z][m * Av + n] = v.x + bb;
            g_dhp[z][(m + 1) * Av + n] = v.y + bb;
        }
    }
}

// --------------------- e[b,p] = relu(enc_proj + Σdh) . fullW + fullb ------------
__global__ void k_e(const float* __restrict__ fullW, const float* __restrict__ fullb) {
    int gw = (blockIdx.x * 256 + threadIdx.x) >> 5;
    int lane = threadIdx.x & 31;
    if (gw >= Bv * Pv) return;
    int b = gw / Pv;
    const float* ep = g_enc_proj + (size_t)gw * Av;
    const float* d0 = g_dhp[0] + b * Av;
    const float* d1 = g_dhp[1] + b * Av;
    const float* d2 = g_dhp[2] + b * Av;
    const float* d3 = g_dhp[3] + b * Av;
    float acc = 0.0f;
#pragma unroll
    for (int k = lane; k < Av; k += 32) {
        float v = ep[k] + ((d0[k] + d1[k]) + (d2[k] + d3[k]));
        acc += fmaxf(v, 0.0f) * fullW[k];
    }
    acc = wsum(acc);
    if (!lane) g_e[gw] = acc + fullb[0];
}

// -------------- softmax (redundant per block) + context (fp16 eo) --------------
__global__ void k_ctx(float* __restrict__ out_alphas, int t) {
    __shared__ float red[256];
    __shared__ float sal[Pv];
    int b = blockIdx.y;
    int tid = threadIdx.x;
    int w = tid >> 5, lane = tid & 31;

    float v = (tid < Pv) ? g_e[b * Pv + tid] : -3.0e38f;
    red[tid] = v; __syncthreads();
    for (int s = 128; s; s >>= 1) {
        if (tid < s) red[tid] = fmaxf(red[tid], red[tid + s]);
        __syncthreads();
    }
    float mx = red[0]; __syncthreads();
    float ex = (tid < Pv) ? expf(v - mx) : 0.0f;
    red[tid] = ex; __syncthreads();
    for (int s = 128; s; s >>= 1) {
        if (tid < s) red[tid] += red[tid + s];
        __syncthreads();
    }
    float inv = 1.0f / red[0];
    if (tid < Pv) {
        float al = ex * inv;
        sal[tid] = al;
        if (blockIdx.x == 0)
            out_alphas[((size_t)b * Tv + t) * Pv + tid] = al;
    }
    __syncthreads();

    int e = blockIdx.x * 8 + w;
    const __half2* row2 =
        (const __half2*)(g_eo16 + (size_t)b * ENCv * Pv + (size_t)e * Pv);
    float acc = 0.0f;
#pragma unroll
    for (int pp = lane; pp < Pv / 2; pp += 32) {
        float2 x = __half22float2(row2[pp]);
        acc += sal[2 * pp] * x.x + sal[2 * pp + 1] * x.y;
    }
    acc = wsum(acc);
    if (!lane) g_xin[b * KIN + e] = acc;
}

// ------------------------------ gates GEMM (K-split) ---------------------------
__global__ void k_gates(const float* __restrict__ Wih, const float* __restrict__ Whh) {
    __shared__ float Xs[2][16][68];
    __shared__ float Ws[2][16][68];
    int n0 = blockIdx.x * 64;
    int z = blockIdx.y;
    int kbase = z * KCHUNK;
    int tid = threadIdx.x;
    int tx = tid & 15, ty = tid >> 4;

    ull acc[2][4];
#pragma unroll
    for (int i = 0; i < 2; i++)
#pragma unroll
        for (int j = 0; j < 4; j++) acc[i][j] = 0ull;

#pragma unroll
    for (int r = 0; r < 4; r++) {
        int mm = ty + 16 * r;
        int kg = kbase + tx;
        Xs[0][tx][mm] = g_xin[mm * KIN + kg];
        int n = n0 + mm;
        Ws[0][tx][mm] = (kg < ENCv) ? Wih[(size_t)n * KIN_W + Ev + kg]
                                    : Whh[(size_t)n * Dv + (kg - ENCv)];
    }
    __syncthreads();
    int buf = 0;
    for (int k0 = 0; k0 < KCHUNK; k0 += 16) {
        float xr[4], wr[4];
        bool more = (k0 + 16 < KCHUNK);
        if (more) {
            int kg = kbase + k0 + 16 + tx;
#pragma unroll
            for (int r = 0; r < 4; r++) {
                int mm = ty + 16 * r;
                xr[r] = g_xin[mm * KIN + kg];
                int n = n0 + mm;
                wr[r] = (kg < ENCv) ? Wih[(size_t)n * KIN_W + Ev + kg]
                                    : Whh[(size_t)n * Dv + (kg - ENCv)];
            }
        }
#pragma unroll
        for (int k = 0; k < 16; k++) {
            ull a0 = *(const ull*)&Xs[buf][k][ty * 4];
            ull a1 = *(const ull*)&Xs[buf][k][ty * 4 + 2];
            float4 bq = *(const float4*)&Ws[buf][k][tx * 4];
            ull bd0 = pk2(bq.x, bq.x), bd1 = pk2(bq.y, bq.y);
            ull bd2 = pk2(bq.z, bq.z), bd3 = pk2(bq.w, bq.w);
            fma2(acc[0][0], a0, bd0); fma2(acc[1][0], a1, bd0);
            fma2(acc[0][1], a0, bd1); fma2(acc[1][1], a1, bd1);
            fma2(acc[0][2], a0, bd2); fma2(acc[1][2], a1, bd2);
            fma2(acc[0][3], a0, bd3); fma2(acc[1][3], a1, bd3);
        }
        if (more) {
#pragma unroll
            for (int r = 0; r < 4; r++) {
                int mm = ty + 16 * r;
                Xs[buf ^ 1][tx][mm] = xr[r];
                Ws[buf ^ 1][tx][mm] = wr[r];
            }
        }
        __syncthreads();
        buf ^= 1;
    }
#pragma unroll
    for (int j = 0; j < 4; j++) {
        int n = n0 + tx * 4 + j;
#pragma unroll
        for (int i = 0; i < 2; i++) {
            float2 v = up2(acc[i][j]);
            int m = ty * 4 + 2 * i;
            g_gpart[z][m * G4D + n] = v.x;
            g_gpart[z][(m + 1) * G4D + n] = v.y;
        }
    }
}

// ------------------------------ LSTM pointwise ---------------------------------
__global__ void k_lstm(const float* __restrict__ bih, const float* __restrict__ bhh, int t) {
    int idx = blockIdx.x * blockDim.x + threadIdx.x;
    if (idx >= Bv * Dv) return;
    int b = idx / Dv, d = idx % Dv;
    const float* ge = g_gemb + ((size_t)t * Bv + b) * G4D;
    float gi = bih[d] + bhh[d] + ge[d];
    float gf = bih[Dv + d] + bhh[Dv + d] + ge[Dv + d];
    float gg = bih[2 * Dv + d] + bhh[2 * Dv + d] + ge[2 * Dv + d];
    float go = bih[3 * Dv + d] + bhh[3 * Dv + d] + ge[3 * Dv + d];
    int base = b * G4D + d;
#pragma unroll
    for (int z = 0; z < KSPLIT; z++) {
        gi += g_gpart[z][base];
        gf += g_gpart[z][base + Dv];
        gg += g_gpart[z][base + 2 * Dv];
        go += g_gpart[z][base + 3 * Dv];
    }
    float c = g_c[idx];
    float cn = sigm(gf) * c + sigm(gi) * tanhf(gg);
    float hn = sigm(go) * tanhf(cn);
    g_c[idx] = cn;
    g_h[idx] = hn;
    g_xin[b * KIN + ENCv + d] = hn;
}

// ------------------------------ fc GEMM (preds) ---------------------------------
__global__ void k_fc(const float* __restrict__ Wf, const float* __restrict__ bf,
                     float* __restrict__ preds, int t) {
    __shared__ float Xs[2][16][68];
    __shared__ float Ws[2][16][68];
    int n0 = blockIdx.x * 64;
    int tid = threadIdx.x;
    int tx = tid & 15, ty = tid >> 4;

    ull acc[2][4];
#pragma unroll
    for (int i = 0; i < 2; i++)
#pragma unroll
        for (int j = 0; j < 4; j++) acc[i][j] = 0ull;

#pragma unroll
    for (int r = 0; r < 4; r++) {
        int mm = ty + 16 * r;
        Xs[0][tx][mm] = g_h[mm * Dv + tx];
        int n = n0 + mm;
        Ws[0][tx][mm] = (n < Vv) ? Wf[(size_t)n * Dv + tx] : 0.0f;
    }
    __syncthreads();
    int buf = 0;
    for (int k0 = 0; k0 < Dv; k0 += 16) {
        float xr[4], wr[4];
        bool more = (k0 + 16 < Dv);
        if (more) {
#pragma unroll
            for (int r = 0; r < 4; r++) {
                int mm = ty + 16 * r;
                xr[r] = g_h[mm * Dv + k0 + 16 + tx];
                int n = n0 + mm;
                wr[r] = (n < Vv) ? Wf[(size_t)n * Dv + k0 + 16 + tx] : 0.0f;
            }
        }
#pragma unroll
        for (int k = 0; k < 16; k++) {
            ull a0 = *(const ull*)&Xs[buf][k][ty * 4];
            ull a1 = *(const ull*)&Xs[buf][k][ty * 4 + 2];
            float4 bq = *(const float4*)&Ws[buf][k][tx * 4];
            ull bd0 = pk2(bq.x, bq.x), bd1 = pk2(bq.y, bq.y);
            ull bd2 = pk2(bq.z, bq.z), bd3 = pk2(bq.w, bq.w);
            fma2(acc[0][0], a0, bd0); fma2(acc[1][0], a1, bd0);
            fma2(acc[0][1], a0, bd1); fma2(acc[1][1], a1, bd1);
            fma2(acc[0][2], a0, bd2); fma2(acc[1][2], a1, bd2);
            fma2(acc[0][3], a0, bd3); fma2(acc[1][3], a1, bd3);
        }
        if (more) {
#pragma unroll
            for (int r = 0; r < 4; r++) {
                int mm = ty + 16 * r;
                Xs[buf ^ 1][tx][mm] = xr[r];
                Ws[buf ^ 1][tx][mm] = wr[r];
            }
        }
        __syncthreads();
        buf ^= 1;
    }
#pragma unroll
    for (int j = 0; j < 4; j++) {
        int n = n0 + tx * 4 + j;
        if (n >= Vv) continue;
        float bb = bf[n];
#pragma unroll
        for (int i = 0; i < 2; i++) {
            float2 v = up2(acc[i][j]);
            int m = ty * 4 + 2 * i;
            preds[((size_t)m * Tv + t) * Vv + n] = v.x + bb;
            preds[((size_t)(m + 1) * Tv + t) * Vv + n] = v.y + bb;
        }
    }
}

// --------------------------------- launcher ------------------------------------
extern "C" void kernel_launch(void* const* d_in, const int* in_sizes, int n_in,
                              void* d_out, int out_size) {
    const float* eo    = (const float*)d_in[0];
    const int*   caps  = (const int*)d_in[1];
    const float* emb   = (const float*)d_in[3];
    const float* encW  = (const float*)d_in[4];
    const float* encb  = (const float*)d_in[5];
    const float* decW  = (const float*)d_in[6];
    const float* decb  = (const float*)d_in[7];
    const float* fullW = (const float*)d_in[8];
    const float* fullb = (const float*)d_in[9];
    const float* ihW   = (const float*)d_in[10];
    const float* ihb   = (const float*)d_in[11];
    const float* icW   = (const float*)d_in[12];
    const float* icb   = (const float*)d_in[13];
    const float* Wih   = (const float*)d_in[14];
    const float* bih   = (const float*)d_in[15];
    const float* Whh   = (const float*)d_in[16];
    const float* bhh   = (const float*)d_in[17];
    const float* fcW   = (const float*)d_in[18];
    const float* fcb   = (const float*)d_in[19];

    float* preds  = (float*)d_out;
    float* alphas = preds + (size_t)Bv * Tv * Vv;

    k_zero_tail<<<(Bv * Vv + Bv * Pv + 255) / 256, 256>>>(preds, alphas);
    k_cvt<<<(Bv * ENCv * Pv / 4 + 255) / 256, 256>>>(eo);
    k_mean<<<(Bv * ENCv * 32 + 255) / 256, 256>>>(eo);
    k_init<<<(2 * Bv * Dv * 32 + 255) / 256, 256>>>(ihW, ihb, icW, icb);
    k_embW<<<dim3(32, 31), 256>>>(caps, emb, Wih);
    k_encproj<<<dim3(98, 4), 256>>>(eo, encW, encb);

    for (int t = 0; t < NSTEP; t++) {
        k_dh<<<dim3(8, DHZ), 256>>>(decW, decb);
        k_e<<<1568, 256>>>(fullW, fullb);
        k_ctx<<<dim3(256, Bv), 256>>>(alphas, t);
        k_gates<<<dim3(32, KSPLIT), 256>>>(Wih, Whh);
        k_lstm<<<(Bv * Dv + 255) / 256, 256>>>(bih, bhh, t);
        k_fc<<<157, 256>>>(fcW, fcb, preds, t);
    }
}

// round 7
// speedup vs baseline: 2.7257x; 1.1802x over previous
#include <cuda_runtime.h>
#include <cuda_fp16.h>
#include <math.h>

#define Bv    64
#define Pv    196
#define ENCv  2048
#define Ev    512
#define Dv    512
#define Av    512
#define Vv    10000
#define Tv    32
#define NSTEP 31
#define G4D   2048          // 4*D
#define KIN   2560          // ENC + D (ctx | h)
#define KIN_W 2560          // Wih row stride (E+ENC)
#define KSPLIT 8
#define KCHUNK 320          // KIN / KSPLIT
#define DHZ   4             // dh K-split
#define DHCH  128           // Dv / DHZ

typedef unsigned long long ull;

// ------------------------- scratch (static device globals) -------------------
__device__ float g_enc_proj[Bv * Pv * Av];        // 25.7 MB
__device__ __half g_eoT[Bv * Pv * ENCv];          // 51.4 MB fp16 transpose [b][p][e]
__device__ __half g_encW16[Av * ENCv];            // 2 MB fp16 enc_att_W
__device__ float g_mean[Bv * ENCv];
__device__ float g_h[Bv * Dv];
__device__ float g_c[Bv * Dv];
__device__ float g_dhp[DHZ][Bv * Av];
__device__ float g_xin[Bv * KIN];                 // [ctx(2048) | h(512)]
__device__ float g_gpart[KSPLIT][Bv * G4D];       // 4 MB
__device__ float g_gemb[NSTEP * Bv * G4D];        // 16.2 MB

// ------------------------------- helpers -------------------------------------
__device__ __forceinline__ ull pk2(float lo, float hi) {
    ull r; asm("mov.b64 %0, {%1, %2};" : "=l"(r) : "f"(lo), "f"(hi)); return r;
}
__device__ __forceinline__ void fma2(ull& d, ull a, ull b) {
    asm("fma.rn.f32x2 %0, %1, %2, %0;" : "+l"(d) : "l"(a), "l"(b));
}
__device__ __forceinline__ float2 up2(ull v) {
    float lo, hi; asm("mov.b64 {%0, %1}, %2;" : "=f"(lo), "=f"(hi) : "l"(v));
    return make_float2(lo, hi);
}
__device__ __forceinline__ float wsum(float v) {
#pragma unroll
    for (int o = 16; o; o >>= 1) v += __shfl_down_sync(0xffffffffu, v, o);
    return v;
}
__device__ __forceinline__ float sigm(float x) { return 1.0f / (1.0f + expf(-x)); }

// --------------------------- zero last timestep -------------------------------
__global__ void k_zero_tail(float* __restrict__ preds, float* __restrict__ alphas) {
    int idx = blockIdx.x * blockDim.x + threadIdx.x;
    if (idx < Bv * Vv) {
        int b = idx / Vv, v = idx % Vv;
        preds[((size_t)b * Tv + (Tv - 1)) * Vv + v] = 0.0f;
    } else {
        int r = idx - Bv * Vv;
        if (r < Bv * Pv) {
            int b = r / Pv, p = r % Pv;
            alphas[((size_t)b * Tv + (Tv - 1)) * Pv + p] = 0.0f;
        }
    }
}

// -------------------- transpose eo -> g_eoT fp16 [b][p][e] ---------------------
__global__ void k_cvtT(const float* __restrict__ eo) {
    __shared__ float tile[32][33];
    int b = blockIdx.z;
    int e0 = blockIdx.x * 32;
    int p0 = blockIdx.y * 32;
    int tx = threadIdx.x, ty = threadIdx.y;
#pragma unroll
    for (int r = 0; r < 4; r++) {
        int e = e0 + ty + 8 * r;
        int p = p0 + tx;
        if (p < Pv)
            tile[ty + 8 * r][tx] = eo[((size_t)b * ENCv + e) * Pv + p];
    }
    __syncthreads();
#pragma unroll
    for (int r = 0; r < 4; r++) {
        int p = p0 + ty + 8 * r;
        int e = e0 + tx;
        if (p < Pv)
            g_eoT[((size_t)b * Pv + p) * ENCv + e] = __float2half(tile[tx][ty + 8 * r]);
    }
}

// -------------------------- convert encW -> fp16 -------------------------------
__global__ void k_cvtW(const float* __restrict__ W) {
    int i = blockIdx.x * blockDim.x + threadIdx.x;   // float4 index
    const int N4 = Av * ENCv / 4;
    if (i >= N4) return;
    float4 v = ((const float4*)W)[i];
    __half2* out = (__half2*)g_encW16;
    out[i * 2]     = __floats2half2_rn(v.x, v.y);
    out[i * 2 + 1] = __floats2half2_rn(v.z, v.w);
}

// -------------------------------- mean over P ---------------------------------
__global__ void k_mean(const float* __restrict__ eo) {
    int gw = (blockIdx.x * blockDim.x + threadIdx.x) >> 5;
    int lane = threadIdx.x & 31;
    if (gw >= Bv * ENCv) return;
    const float* row = eo + (size_t)gw * Pv;
    float acc = 0.0f;
    for (int p = lane; p < Pv; p += 32) acc += row[p];
    acc = wsum(acc);
    if (!lane) g_mean[gw] = acc * (1.0f / (float)Pv);
}

// -------------------------------- h0 / c0 -------------------------------------
__global__ void k_init(const float* __restrict__ Wh, const float* __restrict__ bh,
                       const float* __restrict__ Wc, const float* __restrict__ bc) {
    int gw = (blockIdx.x * blockDim.x + threadIdx.x) >> 5;
    int lane = threadIdx.x & 31;
    if (gw >= 2 * Bv * Dv) return;
    int sel = gw >= Bv * Dv;
    int r = gw - sel * Bv * Dv;
    int b = r / Dv, d = r % Dv;
    const float* W = sel ? Wc : Wh;
    const float* mn = g_mean + (size_t)b * ENCv;
    const float* wr = W + (size_t)d * ENCv;
    float acc = 0.0f;
    for (int k = lane; k < ENCv; k += 32) acc += mn[k] * wr[k];
    acc = wsum(acc);
    if (!lane) {
        float v = acc + (sel ? bc : bh)[d];
        if (sel) g_c[r] = v;
        else { g_h[r] = v; g_xin[b * KIN + ENCv + d] = v; }
    }
}

// -------------------- enc_proj GEMM via HMMA (m16n8k8) -------------------------
// A = g_eoT [12544][2048] fp16, B = g_encW16 [512][2048] fp16, C fp32 + bias.
__global__ __launch_bounds__(256, 2)
void k_encproj_mma(const float* __restrict__ bias) {
    __shared__ __align__(16) __half As[2][128][40];
    __shared__ __align__(16) __half Bs[2][128][40];
    int m0 = blockIdx.x * 128;     // 98 tiles
    int n0 = blockIdx.y * 128;     // 4 tiles
    int tid = threadIdx.x;
    int wid = tid >> 5, lane = tid & 31;
    int wm = wid & 3, wn = wid >> 2;      // warp tile: rows wm*32, cols wn*64
    int g = lane >> 2, tg = lane & 3;

    int lrow = tid >> 1;                  // 0..127
    int lseg = (tid & 1) * 16;            // 0 or 16

    const __half* Ag = g_eoT + (size_t)(m0 + lrow) * ENCv + lseg;
    const __half* Bg = g_encW16 + (size_t)(n0 + lrow) * ENCv + lseg;

    float c[2][8][4];
#pragma unroll
    for (int mt = 0; mt < 2; mt++)
#pragma unroll
        for (int nt = 0; nt < 8; nt++)
#pragma unroll
            for (int q = 0; q < 4; q++) c[mt][nt][q] = 0.0f;

    // prologue
    *(uint4*)&As[0][lrow][lseg]     = *(const uint4*)(Ag);
    *(uint4*)&As[0][lrow][lseg + 8] = *(const uint4*)(Ag + 8);
    *(uint4*)&Bs[0][lrow][lseg]     = *(const uint4*)(Bg);
    *(uint4*)&Bs[0][lrow][lseg + 8] = *(const uint4*)(Bg + 8);
    __syncthreads();

    int buf = 0;
    for (int k0 = 0; k0 < ENCv; k0 += 32) {
        uint4 pa0, pa1, pb0, pb1;
        bool more = (k0 + 32 < ENCv);
        if (more) {
            pa0 = *(const uint4*)(Ag + k0 + 32);
            pa1 = *(const uint4*)(Ag + k0 + 40);
            pb0 = *(const uint4*)(Bg + k0 + 32);
            pb1 = *(const uint4*)(Bg + k0 + 40);
        }
#pragma unroll
        for (int ks = 0; ks < 4; ks++) {
            int kk = ks * 8 + tg * 2;
            unsigned a0[2], a1[2];
#pragma unroll
            for (int mt = 0; mt < 2; mt++) {
                int row = wm * 32 + mt * 16;
                a0[mt] = *(const unsigned*)&As[buf][row + g][kk];
                a1[mt] = *(const unsigned*)&As[buf][row + 8 + g][kk];
            }
#pragma unroll
            for (int nt = 0; nt < 8; nt++) {
                unsigned b0 = *(const unsigned*)&Bs[buf][wn * 64 + nt * 8 + g][kk];
#pragma unroll
                for (int mt = 0; mt < 2; mt++) {
                    asm volatile(
                        "mma.sync.aligned.m16n8k8.row.col.f32.f16.f16.f32 "
                        "{%0,%1,%2,%3}, {%4,%5}, {%6}, {%0,%1,%2,%3};"
                        : "+f"(c[mt][nt][0]), "+f"(c[mt][nt][1]),
                          "+f"(c[mt][nt][2]), "+f"(c[mt][nt][3])
                        : "r"(a0[mt]), "r"(a1[mt]), "r"(b0));
                }
            }
        }
        if (more) {
            *(uint4*)&As[buf ^ 1][lrow][lseg]     = pa0;
            *(uint4*)&As[buf ^ 1][lrow][lseg + 8] = pa1;
            *(uint4*)&Bs[buf ^ 1][lrow][lseg]     = pb0;
            *(uint4*)&Bs[buf ^ 1][lrow][lseg + 8] = pb1;
        }
        __syncthreads();
        buf ^= 1;
    }

#pragma unroll
    for (int nt = 0; nt < 8; nt++) {
        int n = n0 + wn * 64 + nt * 8 + tg * 2;
        float b0f = bias[n], b1f = bias[n + 1];
#pragma unroll
        for (int mt = 0; mt < 2; mt++) {
            int m = m0 + wm * 32 + mt * 16 + g;
            float2 v0 = make_float2(c[mt][nt][0] + b0f, c[mt][nt][1] + b1f);
            float2 v1 = make_float2(c[mt][nt][2] + b0f, c[mt][nt][3] + b1f);
            *(float2*)&g_enc_proj[(size_t)m * Av + n] = v0;
            *(float2*)&g_enc_proj[(size_t)(m + 8) * Av + n] = v1;
        }
    }
}

// ------------------ precompute emb @ Wih_emb.T for all steps -------------------
__global__ void k_embW(const int* __restrict__ caps, const float* __restrict__ emb,
                       const float* __restrict__ Wih) {
    __shared__ float Xs[2][16][68];
    __shared__ float Ws[2][16][68];
    int n0 = blockIdx.x * 64;
    int m0 = blockIdx.y * 64;
    int tid = threadIdx.x;
    int tx = tid & 15, ty = tid >> 4;

    int caprow[4];
#pragma unroll
    for (int r = 0; r < 4; r++) {
        int mm = ty + 16 * r;
        int m = m0 + mm;
        int b = m & 63, t = m >> 6;
        caprow[r] = caps[b * Tv + t];
    }

    ull acc[2][4];
#pragma unroll
    for (int i = 0; i < 2; i++)
#pragma unroll
        for (int j = 0; j < 4; j++) acc[i][j] = 0ull;

#pragma unroll
    for (int r = 0; r < 4; r++) {
        Xs[0][tx][ty + 16 * r] = emb[(size_t)caprow[r] * Ev + tx];
        Ws[0][tx][ty + 16 * r] = Wih[(size_t)(n0 + ty + 16 * r) * KIN_W + tx];
    }
    __syncthreads();
    int buf = 0;
    for (int k0 = 0; k0 < Ev; k0 += 16) {
        float xr[4], wr[4];
        bool more = (k0 + 16 < Ev);
        if (more) {
#pragma unroll
            for (int r = 0; r < 4; r++) {
                xr[r] = emb[(size_t)caprow[r] * Ev + k0 + 16 + tx];
                wr[r] = Wih[(size_t)(n0 + ty + 16 * r) * KIN_W + k0 + 16 + tx];
            }
        }
#pragma unroll
        for (int k = 0; k < 16; k++) {
            ull a0 = *(const ull*)&Xs[buf][k][ty * 4];
            ull a1 = *(const ull*)&Xs[buf][k][ty * 4 + 2];
            float4 bq = *(const float4*)&Ws[buf][k][tx * 4];
            ull bd0 = pk2(bq.x, bq.x), bd1 = pk2(bq.y, bq.y);
            ull bd2 = pk2(bq.z, bq.z), bd3 = pk2(bq.w, bq.w);
            fma2(acc[0][0], a0, bd0); fma2(acc[1][0], a1, bd0);
            fma2(acc[0][1], a0, bd1); fma2(acc[1][1], a1, bd1);
            fma2(acc[0][2], a0, bd2); fma2(acc[1][2], a1, bd2);
            fma2(acc[0][3], a0, bd3); fma2(acc[1][3], a1, bd3);
        }
        if (more) {
#pragma unroll
            for (int r = 0; r < 4; r++) {
                Xs[buf ^ 1][tx][ty + 16 * r] = xr[r];
                Ws[buf ^ 1][tx][ty + 16 * r] = wr[r];
            }
        }
        __syncthreads();
        buf ^= 1;
    }
#pragma unroll
    for (int j = 0; j < 4; j++) {
        int n = n0 + tx * 4 + j;
#pragma unroll
        for (int i = 0; i < 2; i++) {
            float2 v = up2(acc[i][j]);
            int m = m0 + ty * 4 + 2 * i;
            g_gemb[(size_t)m * G4D + n] = v.x;
            g_gemb[(size_t)(m + 1) * G4D + n] = v.y;
        }
    }
}

// ------------------ dh partials: K-split 4 (preamble kernel) -------------------
__global__ void k_dh(const float* __restrict__ decW, const float* __restrict__ decb) {
    __shared__ float Xs[2][16][68];
    __shared__ float Ws[2][16][68];
    int n0 = blockIdx.x * 64;
    int z = blockIdx.y;
    int kbase = z * DHCH;
    int tid = threadIdx.x;
    int tx = tid & 15, ty = tid >> 4;

    ull acc[2][4];
#pragma unroll
    for (int i = 0; i < 2; i++)
#pragma unroll
        for (int j = 0; j < 4; j++) acc[i][j] = 0ull;

#pragma unroll
    for (int r = 0; r < 4; r++) {
        int mm = ty + 16 * r;
        Xs[0][tx][mm] = g_h[mm * Dv + kbase + tx];
        Ws[0][tx][mm] = decW[(size_t)(n0 + mm) * Dv + kbase + tx];
    }
    __syncthreads();
    int buf = 0;
    for (int k0 = 0; k0 < DHCH; k0 += 16) {
        float xr[4], wr[4];
        bool more = (k0 + 16 < DHCH);
        if (more) {
#pragma unroll
            for (int r = 0; r < 4; r++) {
                int mm = ty + 16 * r;
                xr[r] = g_h[mm * Dv + kbase + k0 + 16 + tx];
                wr[r] = decW[(size_t)(n0 + mm) * Dv + kbase + k0 + 16 + tx];
            }
        }
#pragma unroll
        for (int k = 0; k < 16; k++) {
            ull a0 = *(const ull*)&Xs[buf][k][ty * 4];
            ull a1 = *(const ull*)&Xs[buf][k][ty * 4 + 2];
            float4 bq = *(const float4*)&Ws[buf][k][tx * 4];
            ull bd0 = pk2(bq.x, bq.x), bd1 = pk2(bq.y, bq.y);
            ull bd2 = pk2(bq.z, bq.z), bd3 = pk2(bq.w, bq.w);
            fma2(acc[0][0], a0, bd0); fma2(acc[1][0], a1, bd0);
            fma2(acc[0][1], a0, bd1); fma2(acc[1][1], a1, bd1);
            fma2(acc[0][2], a0, bd2); fma2(acc[1][2], a1, bd2);
            fma2(acc[0][3], a0, bd3); fma2(acc[1][3], a1, bd3);
        }
        if (more) {
#pragma unroll
            for (int r = 0; r < 4; r++) {
                int mm = ty + 16 * r;
                Xs[buf ^ 1][tx][mm] = xr[r];
                Ws[buf ^ 1][tx][mm] = wr[r];
            }
        }
        __syncthreads();
        buf ^= 1;
    }
#pragma unroll
    for (int j = 0; j < 4; j++) {
        int n = n0 + tx * 4 + j;
        float bb = (z == 0) ? decb[n] : 0.0f;
#pragma unroll
        for (int i = 0; i < 2; i++) {
            float2 v = up2(acc[i][j]);
            int m = ty * 4 + 2 * i;
            g_dhp[z][m * Av + n] = v.x + bb;
            g_dhp[z][(m + 1) * Av + n] = v.y + bb;
        }
    }
}

// ----------- fused attention: e + softmax + context (one block per b) ----------
__global__ void k_att(const float* __restrict__ fullW, const float* __restrict__ fullb,
                      float* __restrict__ out_alphas, int t) {
    __shared__ float s_dh[Av];
    __shared__ float s_fw[Av];
    __shared__ float s_e[256];
    __shared__ float red[256];
    __shared__ float s_al[256];
    int b = blockIdx.x;
    int tid = threadIdx.x;       // 0..511
    int w = tid >> 5, lane = tid & 31;

    if (tid < Av) {
        int o = b * Av + tid;
        s_dh[tid] = (g_dhp[0][o] + g_dhp[1][o]) + (g_dhp[2][o] + g_dhp[3][o]);
        s_fw[tid] = fullW[tid];
    }
    __syncthreads();

    // e[p] = relu(enc_proj[b,p,:] + dh) . fullW + fullb
    for (int p = w; p < Pv; p += 16) {
        const float* ep = g_enc_proj + (size_t)(b * Pv + p) * Av;
        float acc = 0.0f;
#pragma unroll
        for (int k = lane; k < Av; k += 32) {
            float v = ep[k] + s_dh[k];
            acc += fmaxf(v, 0.0f) * s_fw[k];
        }
        acc = wsum(acc);
        if (!lane) s_e[p] = acc + fullb[0];
    }
    __syncthreads();

    // softmax over P=196
    float v = (tid < Pv) ? s_e[tid] : -3.0e38f;
    if (tid < 256) red[tid] = v;
    __syncthreads();
    for (int s = 128; s; s >>= 1) {
        if (tid < s) red[tid] = fmaxf(red[tid], red[tid + s]);
        __syncthreads();
    }
    float mx = red[0];
    __syncthreads();
    float ex = (tid < Pv) ? expf(v - mx) : 0.0f;
    if (tid < 256) red[tid] = ex;
    __syncthreads();
    for (int s = 128; s; s >>= 1) {
        if (tid < s) red[tid] += red[tid + s];
        __syncthreads();
    }
    float inv = 1.0f / red[0];
    if (tid < Pv) {
        float al = ex * inv;
        s_al[tid] = al;
        out_alphas[((size_t)b * Tv + t) * Pv + tid] = al;
    }
    __syncthreads();

    // context from eoT: thread handles e = tid + 512j
    const __half* base = g_eoT + (size_t)b * Pv * ENCv + tid;
    float a0 = 0.f, a1 = 0.f, a2 = 0.f, a3 = 0.f;
    for (int p = 0; p < Pv; p++) {
        float al = s_al[p];
        const __half* r = base + (size_t)p * ENCv;
        a0 += al * __half2float(r[0]);
        a1 += al * __half2float(r[512]);
        a2 += al * __half2float(r[1024]);
        a3 += al * __half2float(r[1536]);
    }
    g_xin[b * KIN + tid]        = a0;
    g_xin[b * KIN + 512 + tid]  = a1;
    g_xin[b * KIN + 1024 + tid] = a2;
    g_xin[b * KIN + 1536 + tid] = a3;
}

// ------------------------------ gates GEMM (K-split) ---------------------------
__global__ void k_gates(const float* __restrict__ Wih, const float* __restrict__ Whh) {
    __shared__ float Xs[2][16][68];
    __shared__ float Ws[2][16][68];
    int n0 = blockIdx.x * 64;
    int z = blockIdx.y;
    int kbase = z * KCHUNK;
    int tid = threadIdx.x;
    int tx = tid & 15, ty = tid >> 4;

    ull acc[2][4];
#pragma unroll
    for (int i = 0; i < 2; i++)
#pragma unroll
        for (int j = 0; j < 4; j++) acc[i][j] = 0ull;

#pragma unroll
    for (int r = 0; r < 4; r++) {
        int mm = ty + 16 * r;
        int kg = kbase + tx;
        Xs[0][tx][mm] = g_xin[mm * KIN + kg];
        int n = n0 + mm;
        Ws[0][tx][mm] = (kg < ENCv) ? Wih[(size_t)n * KIN_W + Ev + kg]
                                    : Whh[(size_t)n * Dv + (kg - ENCv)];
    }
    __syncthreads();
    int buf = 0;
    for (int k0 = 0; k0 < KCHUNK; k0 += 16) {
        float xr[4], wr[4];
        bool more = (k0 + 16 < KCHUNK);
        if (more) {
            int kg = kbase + k0 + 16 + tx;
#pragma unroll
            for (int r = 0; r < 4; r++) {
                int mm = ty + 16 * r;
                xr[r] = g_xin[mm * KIN + kg];
                int n = n0 + mm;
                wr[r] = (kg < ENCv) ? Wih[(size_t)n * KIN_W + Ev + kg]
                                    : Whh[(size_t)n * Dv + (kg - ENCv)];
            }
        }
#pragma unroll
        for (int k = 0; k < 16; k++) {
            ull a0 = *(const ull*)&Xs[buf][k][ty * 4];
            ull a1 = *(const ull*)&Xs[buf][k][ty * 4 + 2];
            float4 bq = *(const float4*)&Ws[buf][k][tx * 4];
            ull bd0 = pk2(bq.x, bq.x), bd1 = pk2(bq.y, bq.y);
            ull bd2 = pk2(bq.z, bq.z), bd3 = pk2(bq.w, bq.w);
            fma2(acc[0][0], a0, bd0); fma2(acc[1][0], a1, bd0);
            fma2(acc[0][1], a0, bd1); fma2(acc[1][1], a1, bd1);
            fma2(acc[0][2], a0, bd2); fma2(acc[1][2], a1, bd2);
            fma2(acc[0][3], a0, bd3); fma2(acc[1][3], a1, bd3);
        }
        if (more) {
#pragma unroll
            for (int r = 0; r < 4; r++) {
                int mm = ty + 16 * r;
                Xs[buf ^ 1][tx][mm] = xr[r];
                Ws[buf ^ 1][tx][mm] = wr[r];
            }
        }
        __syncthreads();
        buf ^= 1;
    }
#pragma unroll
    for (int j = 0; j < 4; j++) {
        int n = n0 + tx * 4 + j;
#pragma unroll
        for (int i = 0; i < 2; i++) {
            float2 v = up2(acc[i][j]);
            int m = ty * 4 + 2 * i;
            g_gpart[z][m * G4D + n] = v.x;
            g_gpart[z][(m + 1) * G4D + n] = v.y;
        }
    }
}

// ------------------------------ LSTM pointwise ---------------------------------
__global__ void k_lstm(const float* __restrict__ bih, const float* __restrict__ bhh, int t) {
    int idx = blockIdx.x * blockDim.x + threadIdx.x;
    if (idx >= Bv * Dv) return;
    int b = idx / Dv, d = idx % Dv;
    const float* ge = g_gemb + ((size_t)t * Bv + b) * G4D;
    float gi = bih[d] + bhh[d] + ge[d];
    float gf = bih[Dv + d] + bhh[Dv + d] + ge[Dv + d];
    float gg = bih[2 * Dv + d] + bhh[2 * Dv + d] + ge[2 * Dv + d];
    float go = bih[3 * Dv + d] + bhh[3 * Dv + d] + ge[3 * Dv + d];
    int base = b * G4D + d;
#pragma unroll
    for (int z = 0; z < KSPLIT; z++) {
        gi += g_gpart[z][base];
        gf += g_gpart[z][base + Dv];
        gg += g_gpart[z][base + 2 * Dv];
        go += g_gpart[z][base + 3 * Dv];
    }
    float c = g_c[idx];
    float cn = sigm(gf) * c + sigm(gi) * tanhf(gg);
    float hn = sigm(go) * tanhf(cn);
    g_c[idx] = cn;
    g_h[idx] = hn;
    g_xin[b * KIN + ENCv + d] = hn;
}

// -------------------- fused fc (preds) + dh for next step ----------------------
__global__ void k_fcdh(const float* __restrict__ Wf, const float* __restrict__ bf,
                       const float* __restrict__ decW, const float* __restrict__ decb,
                       float* __restrict__ preds, int t) {
    __shared__ float Xs[2][16][68];
    __shared__ float Ws[2][16][68];
    int tid = threadIdx.x;
    int tx = tid & 15, ty = tid >> 4;

    if (blockIdx.x < 157) {
        // ------------------------------ fc path -------------------------------
        int n0 = blockIdx.x * 64;
        ull acc[2][4];
#pragma unroll
        for (int i = 0; i < 2; i++)
#pragma unroll
            for (int j = 0; j < 4; j++) acc[i][j] = 0ull;

#pragma unroll
        for (int r = 0; r < 4; r++) {
            int mm = ty + 16 * r;
            Xs[0][tx][mm] = g_h[mm * Dv + tx];
            int n = n0 + mm;
            Ws[0][tx][mm] = (n < Vv) ? Wf[(size_t)n * Dv + tx] : 0.0f;
        }
        __syncthreads();
        int buf = 0;
        for (int k0 = 0; k0 < Dv; k0 += 16) {
            float xr[4], wr[4];
            bool more = (k0 + 16 < Dv);
            if (more) {
#pragma unroll
                for (int r = 0; r < 4; r++) {
                    int mm = ty + 16 * r;
                    xr[r] = g_h[mm * Dv + k0 + 16 + tx];
                    int n = n0 + mm;
                    wr[r] = (n < Vv) ? Wf[(size_t)n * Dv + k0 + 16 + tx] : 0.0f;
                }
            }
#pragma unroll
            for (int k = 0; k < 16; k++) {
                ull a0 = *(const ull*)&Xs[buf][k][ty * 4];
                ull a1 = *(const ull*)&Xs[buf][k][ty * 4 + 2];
                float4 bq = *(const float4*)&Ws[buf][k][tx * 4];
                ull bd0 = pk2(bq.x, bq.x), bd1 = pk2(bq.y, bq.y);
                ull bd2 = pk2(bq.z, bq.z), bd3 = pk2(bq.w, bq.w);
                fma2(acc[0][0], a0, bd0); fma2(acc[1][0], a1, bd0);
                fma2(acc[0][1], a0, bd1); fma2(acc[1][1], a1, bd1);
                fma2(acc[0][2], a0, bd2); fma2(acc[1][2], a1, bd2);
                fma2(acc[0][3], a0, bd3); fma2(acc[1][3], a1, bd3);
            }
            if (more) {
#pragma unroll
                for (int r = 0; r < 4; r++) {
                    int mm = ty + 16 * r;
                    Xs[buf ^ 1][tx][mm] = xr[r];
                    Ws[buf ^ 1][tx][mm] = wr[r];
                }
            }
            __syncthreads();
            buf ^= 1;
        }
#pragma unroll
        for (int j = 0; j < 4; j++) {
            int n = n0 + tx * 4 + j;
            if (n >= Vv) continue;
            float bb = bf[n];
#pragma unroll
            for (int i = 0; i < 2; i++) {
                float2 v = up2(acc[i][j]);
                int m = ty * 4 + 2 * i;
                preds[((size_t)m * Tv + t) * Vv + n] = v.x + bb;
                preds[((size_t)(m + 1) * Tv + t) * Vv + n] = v.y + bb;
            }
        }
    } else {
        // ------------------------------ dh path -------------------------------
        int q = blockIdx.x - 157;        // 0..31
        int n0 = (q & 7) * 64;
        int z = q >> 3;
        int kbase = z * DHCH;

        ull acc[2][4];
#pragma unroll
        for (int i = 0; i < 2; i++)
#pragma unroll
            for (int j = 0; j < 4; j++) acc[i][j] = 0ull;

#pragma unroll
        for (int r = 0; r < 4; r++) {
            int mm = ty + 16 * r;
            Xs[0][tx][mm] = g_h[mm * Dv + kbase + tx];
            Ws[0][tx][mm] = decW[(size_t)(n0 + mm) * Dv + kbase + tx];
        }
        __syncthreads();
        int buf = 0;
        for (int k0 = 0; k0 < DHCH; k0 += 16) {
            float xr[4], wr[4];
            bool more = (k0 + 16 < DHCH);
            if (more) {
#pragma unroll
                for (int r = 0; r < 4; r++) {
                    int mm = ty + 16 * r;
                    xr[r] = g_h[mm * Dv + kbase + k0 + 16 + tx];
                    wr[r] = decW[(size_t)(n0 + mm) * Dv + kbase + k0 + 16 + tx];
                }
            }
#pragma unroll
            for (int k = 0; k < 16; k++) {
                ull a0 = *(const ull*)&Xs[buf][k][ty * 4];
                ull a1 = *(const ull*)&Xs[buf][k][ty * 4 + 2];
                float4 bq = *(const float4*)&Ws[buf][k][tx * 4];
                ull bd0 = pk2(bq.x, bq.x), bd1 = pk2(bq.y, bq.y);
                ull bd2 = pk2(bq.z, bq.z), bd3 = pk2(bq.w, bq.w);
                fma2(acc[0][0], a0, bd0); fma2(acc[1][0], a1, bd0);
                fma2(acc[0][1], a0, bd1); fma2(acc[1][1], a1, bd1);
                fma2(acc[0][2], a0, bd2); fma2(acc[1][2], a1, bd2);
                fma2(acc[0][3], a0, bd3); fma2(acc[1][3], a1, bd3);
            }
            if (more) {
#pragma unroll
                for (int r = 0; r < 4; r++) {
                    int mm = ty + 16 * r;
                    Xs[buf ^ 1][tx][mm] = xr[r];
                    Ws[buf ^ 1][tx][mm] = wr[r];
                }
            }
            __syncthreads();
            buf ^= 1;
        }
#pragma unroll
        for (int j = 0; j < 4; j++) {
            int n = n0 + tx * 4 + j;
            float bb = (z == 0) ? decb[n] : 0.0f;
#pragma unroll
            for (int i = 0; i < 2; i++) {
                float2 v = up2(acc[i][j]);
                int m = ty * 4 + 2 * i;
                g_dhp[z][m * Av + n] = v.x + bb;
                g_dhp[z][(m + 1) * Av + n] = v.y + bb;
            }
        }
    }
}

// --------------------------------- launcher ------------------------------------
extern "C" void kernel_launch(void* const* d_in, const int* in_sizes, int n_in,
                              void* d_out, int out_size) {
    const float* eo    = (const float*)d_in[0];
    const int*   caps  = (const int*)d_in[1];
    const float* emb   = (const float*)d_in[3];
    const float* encW  = (const float*)d_in[4];
    const float* encb  = (const float*)d_in[5];
    const float* decW  = (const float*)d_in[6];
    const float* decb  = (const float*)d_in[7];
    const float* fullW = (const float*)d_in[8];
    const float* fullb = (const float*)d_in[9];
    const float* ihW   = (const float*)d_in[10];
    const float* ihb   = (const float*)d_in[11];
    const float* icW   = (const float*)d_in[12];
    const float* icb   = (const float*)d_in[13];
    const float* Wih   = (const float*)d_in[14];
    const float* bih   = (const float*)d_in[15];
    const float* Whh   = (const float*)d_in[16];
    const float* bhh   = (const float*)d_in[17];
    const float* fcW   = (const float*)d_in[18];
    const float* fcb   = (const float*)d_in[19];

    float* preds  = (float*)d_out;
    float* alphas = preds + (size_t)Bv * Tv * Vv;

    k_zero_tail<<<(Bv * Vv + Bv * Pv + 255) / 256, 256>>>(preds, alphas);
    k_cvtT<<<dim3(ENCv / 32, (Pv + 31) / 32, Bv), dim3(32, 8)>>>(eo);
    k_cvtW<<<(Av * ENCv / 4 + 255) / 256, 256>>>(encW);
    k_mean<<<(Bv * ENCv * 32 + 255) / 256, 256>>>(eo);
    k_init<<<(2 * Bv * Dv * 32 + 255) / 256, 256>>>(ihW, ihb, icW, icb);
    k_embW<<<dim3(32, 31), 256>>>(caps, emb, Wih);
    k_encproj_mma<<<dim3(98, 4), 256>>>(encb);
    k_dh<<<dim3(8, DHZ), 256>>>(decW, decb);

    for (int t = 0; t < NSTEP; t++) {
        k_att<<<Bv, 512>>>(fullW, fullb, alphas, t);
        k_gates<<<dim3(32, KSPLIT), 256>>>(Wih, Whh);
        k_lstm<<<(Bv * Dv + 255) / 256, 256>>>(bih, bhh, t);
        k_fcdh<<<189, 256>>>(fcW, fcb, decW, decb, preds, t);
    }
}

// round 8
// speedup vs baseline: 4.3986x; 1.6137x over previous
#include <cuda_runtime.h>
#include <cuda_fp16.h>
#include <math.h>

#define Bv    64
#define Pv    196
#define ENCv  2048
#define Ev    512
#define Dv    512
#define Av    512
#define Vv    10000
#define Tv    32
#define NSTEP 31
#define G4D   2048          // 4*D
#define KIN   2560          // ENC + D (ctx | h)
#define KIN_W 2560          // Wih row stride (E+ENC)
#define GZ    4             // gates K-split
#define GCH   640           // KIN / GZ
#define DHZ   4             // dh K-split
#define DHCH  128           // Dv / DHZ
#define NFCPAD 10112        // fc rows padded to 79*128

typedef unsigned long long ull;

// ------------------------- scratch (static device globals) -------------------
__device__ float g_enc_proj[Bv * Pv * Av];        // 25.7 MB
__device__ __half g_eoT[Bv * Pv * ENCv];          // 51.4 MB fp16 transpose [b][p][e]
__device__ __half g_encW16[Av * ENCv];            // 2 MB
__device__ __half g_Wg16[G4D * KIN];              // 10.5 MB  [Wih_ctx | Whh]
__device__ __half g_fcW16[NFCPAD * Dv];           // 10.3 MB  padded fc weight
__device__ __half g_xin16[Bv * KIN];              // fp16 [ctx | h]
__device__ float g_mean[Bv * ENCv];
__device__ float g_h[Bv * Dv];
__device__ float g_c[Bv * Dv];
__device__ float g_dhp[DHZ][Bv * Av];
__device__ float g_gpart[GZ][Bv * G4D];
__device__ float g_gemb[NSTEP * Bv * G4D];        // 16.2 MB

// ------------------------------- helpers -------------------------------------
__device__ __forceinline__ ull pk2(float lo, float hi) {
    ull r; asm("mov.b64 %0, {%1, %2};" : "=l"(r) : "f"(lo), "f"(hi)); return r;
}
__device__ __forceinline__ void fma2(ull& d, ull a, ull b) {
    asm("fma.rn.f32x2 %0, %1, %2, %0;" : "+l"(d) : "l"(a), "l"(b));
}
__device__ __forceinline__ float2 up2(ull v) {
    float lo, hi; asm("mov.b64 {%0, %1}, %2;" : "=f"(lo), "=f"(hi) : "l"(v));
    return make_float2(lo, hi);
}
__device__ __forceinline__ float wsum(float v) {
#pragma unroll
    for (int o = 16; o; o >>= 1) v += __shfl_down_sync(0xffffffffu, v, o);
    return v;
}
__device__ __forceinline__ float sigm(float x) { return 1.0f / (1.0f + expf(-x)); }

#define MMA_K8(c, a0, a1, b0) \
    asm volatile("mma.sync.aligned.m16n8k8.row.col.f32.f16.f16.f32 " \
                 "{%0,%1,%2,%3}, {%4,%5}, {%6}, {%0,%1,%2,%3};" \
                 : "+f"((c)[0]), "+f"((c)[1]), "+f"((c)[2]), "+f"((c)[3]) \
                 : "r"(a0), "r"(a1), "r"(b0))

// --------------------------- zero last timestep -------------------------------
__global__ void k_zero_tail(float* __restrict__ preds, float* __restrict__ alphas) {
    int idx = blockIdx.x * blockDim.x + threadIdx.x;
    if (idx < Bv * Vv) {
        int b = idx / Vv, v = idx % Vv;
        preds[((size_t)b * Tv + (Tv - 1)) * Vv + v] = 0.0f;
    } else {
        int r = idx - Bv * Vv;
        if (r < Bv * Pv) {
            int b = r / Pv, p = r % Pv;
            alphas[((size_t)b * Tv + (Tv - 1)) * Pv + p] = 0.0f;
        }
    }
}

// -------------------- transpose eo -> g_eoT fp16 [b][p][e] ---------------------
__global__ void k_cvtT(const float* __restrict__ eo) {
    __shared__ float tile[32][33];
    int b = blockIdx.z;
    int e0 = blockIdx.x * 32;
    int p0 = blockIdx.y * 32;
    int tx = threadIdx.x, ty = threadIdx.y;
#pragma unroll
    for (int r = 0; r < 4; r++) {
        int e = e0 + ty + 8 * r;
        int p = p0 + tx;
        if (p < Pv)
            tile[ty + 8 * r][tx] = eo[((size_t)b * ENCv + e) * Pv + p];
    }
    __syncthreads();
#pragma unroll
    for (int r = 0; r < 4; r++) {
        int p = p0 + ty + 8 * r;
        int e = e0 + tx;
        if (p < Pv)
            g_eoT[((size_t)b * Pv + p) * ENCv + e] = __float2half(tile[tx][ty + 8 * r]);
    }
}

// -------------------------- convert encW -> fp16 -------------------------------
__global__ void k_cvtW(const float* __restrict__ W) {
    int i = blockIdx.x * blockDim.x + threadIdx.x;
    const int N4 = Av * ENCv / 4;
    if (i >= N4) return;
    float4 v = ((const float4*)W)[i];
    __half2* out = (__half2*)g_encW16;
    out[i * 2]     = __floats2half2_rn(v.x, v.y);
    out[i * 2 + 1] = __floats2half2_rn(v.z, v.w);
}

// ------------------- build g_Wg16 = [Wih_ctx | Whh] fp16 -----------------------
__global__ void k_cvt_Wg(const float* __restrict__ Wih, const float* __restrict__ Whh) {
    int i = blockIdx.x * blockDim.x + threadIdx.x;   // half2 index
    const int N2 = G4D * KIN / 2;
    if (i >= N2) return;
    int n = i / (KIN / 2);
    int k = (i % (KIN / 2)) * 2;
    float v0, v1;
    if (k < ENCv) {
        v0 = Wih[(size_t)n * KIN_W + Ev + k];
        v1 = Wih[(size_t)n * KIN_W + Ev + k + 1];
    } else {
        v0 = Whh[(size_t)n * Dv + (k - ENCv)];
        v1 = Whh[(size_t)n * Dv + (k - ENCv) + 1];
    }
    ((__half2*)g_Wg16)[i] = __floats2half2_rn(v0, v1);
}

// ------------------------ build g_fcW16 (padded) fp16 --------------------------
__global__ void k_cvt_fcW(const float* __restrict__ Wf) {
    int i = blockIdx.x * blockDim.x + threadIdx.x;   // half2 index
    const int N2 = NFCPAD * Dv / 2;
    if (i >= N2) return;
    int n = i / (Dv / 2);
    int k = (i % (Dv / 2)) * 2;
    float v0 = 0.f, v1 = 0.f;
    if (n < Vv) {
        v0 = Wf[(size_t)n * Dv + k];
        v1 = Wf[(size_t)n * Dv + k + 1];
    }
    ((__half2*)g_fcW16)[i] = __floats2half2_rn(v0, v1);
}

// -------------------------------- mean over P ---------------------------------
__global__ void k_mean(const float* __restrict__ eo) {
    int gw = (blockIdx.x * blockDim.x + threadIdx.x) >> 5;
    int lane = threadIdx.x & 31;
    if (gw >= Bv * ENCv) return;
    const float* row = eo + (size_t)gw * Pv;
    float acc = 0.0f;
    for (int p = lane; p < Pv; p += 32) acc += row[p];
    acc = wsum(acc);
    if (!lane) g_mean[gw] = acc * (1.0f / (float)Pv);
}

// -------------------------------- h0 / c0 -------------------------------------
__global__ void k_init(const float* __restrict__ Wh, const float* __restrict__ bh,
                       const float* __restrict__ Wc, const float* __restrict__ bc) {
    int gw = (blockIdx.x * blockDim.x + threadIdx.x) >> 5;
    int lane = threadIdx.x & 31;
    if (gw >= 2 * Bv * Dv) return;
    int sel = gw >= Bv * Dv;
    int r = gw - sel * Bv * Dv;
    int b = r / Dv, d = r % Dv;
    const float* W = sel ? Wc : Wh;
    const float* mn = g_mean + (size_t)b * ENCv;
    const float* wr = W + (size_t)d * ENCv;
    float acc = 0.0f;
    for (int k = lane; k < ENCv; k += 32) acc += mn[k] * wr[k];
    acc = wsum(acc);
    if (!lane) {
        float v = acc + (sel ? bc : bh)[d];
        if (sel) g_c[r] = v;
        else { g_h[r] = v; g_xin16[b * KIN + ENCv + d] = __float2half(v); }
    }
}

// -------------------- enc_proj GEMM via HMMA (m16n8k8) -------------------------
__global__ __launch_bounds__(256, 2)
void k_encproj_mma(const float* __restrict__ bias) {
    __shared__ __align__(16) __half As[2][128][40];
    __shared__ __align__(16) __half Bs[2][128][40];
    int m0 = blockIdx.x * 128;
    int n0 = blockIdx.y * 128;
    int tid = threadIdx.x;
    int wid = tid >> 5, lane = tid & 31;
    int wm = wid & 3, wn = wid >> 2;
    int g = lane >> 2, tg = lane & 3;

    int lrow = tid >> 1;
    int lseg = (tid & 1) * 16;

    const __half* Ag = g_eoT + (size_t)(m0 + lrow) * ENCv + lseg;
    const __half* Bg = g_encW16 + (size_t)(n0 + lrow) * ENCv + lseg;

    float c[2][8][4];
#pragma unroll
    for (int mt = 0; mt < 2; mt++)
#pragma unroll
        for (int nt = 0; nt < 8; nt++)
#pragma unroll
            for (int q = 0; q < 4; q++) c[mt][nt][q] = 0.0f;

    *(uint4*)&As[0][lrow][lseg]     = *(const uint4*)(Ag);
    *(uint4*)&As[0][lrow][lseg + 8] = *(const uint4*)(Ag + 8);
    *(uint4*)&Bs[0][lrow][lseg]     = *(const uint4*)(Bg);
    *(uint4*)&Bs[0][lrow][lseg + 8] = *(const uint4*)(Bg + 8);
    __syncthreads();

    int buf = 0;
    for (int k0 = 0; k0 < ENCv; k0 += 32) {
        uint4 pa0, pa1, pb0, pb1;
        bool more = (k0 + 32 < ENCv);
        if (more) {
            pa0 = *(const uint4*)(Ag + k0 + 32);
            pa1 = *(const uint4*)(Ag + k0 + 40);
            pb0 = *(const uint4*)(Bg + k0 + 32);
            pb1 = *(const uint4*)(Bg + k0 + 40);
        }
#pragma unroll
        for (int ks = 0; ks < 4; ks++) {
            int kk = ks * 8 + tg * 2;
            unsigned a0[2], a1[2];
#pragma unroll
            for (int mt = 0; mt < 2; mt++) {
                int row = wm * 32 + mt * 16;
                a0[mt] = *(const unsigned*)&As[buf][row + g][kk];
                a1[mt] = *(const unsigned*)&As[buf][row + 8 + g][kk];
            }
#pragma unroll
            for (int nt = 0; nt < 8; nt++) {
                unsigned b0 = *(const unsigned*)&Bs[buf][wn * 64 + nt * 8 + g][kk];
#pragma unroll
                for (int mt = 0; mt < 2; mt++) MMA_K8(c[mt][nt], a0[mt], a1[mt], b0);
            }
        }
        if (more) {
            *(uint4*)&As[buf ^ 1][lrow][lseg]     = pa0;
            *(uint4*)&As[buf ^ 1][lrow][lseg + 8] = pa1;
            *(uint4*)&Bs[buf ^ 1][lrow][lseg]     = pb0;
            *(uint4*)&Bs[buf ^ 1][lrow][lseg + 8] = pb1;
        }
        __syncthreads();
        buf ^= 1;
    }

#pragma unroll
    for (int nt = 0; nt < 8; nt++) {
        int n = n0 + wn * 64 + nt * 8 + tg * 2;
        float b0f = bias[n], b1f = bias[n + 1];
#pragma unroll
        for (int mt = 0; mt < 2; mt++) {
            int m = m0 + wm * 32 + mt * 16 + g;
            float2 v0 = make_float2(c[mt][nt][0] + b0f, c[mt][nt][1] + b1f);
            float2 v1 = make_float2(c[mt][nt][2] + b0f, c[mt][nt][3] + b1f);
            *(float2*)&g_enc_proj[(size_t)m * Av + n] = v0;
            *(float2*)&g_enc_proj[(size_t)(m + 8) * Av + n] = v1;
        }
    }
}

// ------------------ precompute emb @ Wih_emb.T for all steps -------------------
__global__ void k_embW(const int* __restrict__ caps, const float* __restrict__ emb,
                       const float* __restrict__ Wih) {
    __shared__ float Xs[2][16][68];
    __shared__ float Ws[2][16][68];
    int n0 = blockIdx.x * 64;
    int m0 = blockIdx.y * 64;
    int tid = threadIdx.x;
    int tx = tid & 15, ty = tid >> 4;

    int caprow[4];
#pragma unroll
    for (int r = 0; r < 4; r++) {
        int mm = ty + 16 * r;
        int m = m0 + mm;
        int b = m & 63, t = m >> 6;
        caprow[r] = caps[b * Tv + t];
    }

    ull acc[2][4];
#pragma unroll
    for (int i = 0; i < 2; i++)
#pragma unroll
        for (int j = 0; j < 4; j++) acc[i][j] = 0ull;

#pragma unroll
    for (int r = 0; r < 4; r++) {
        Xs[0][tx][ty + 16 * r] = emb[(size_t)caprow[r] * Ev + tx];
        Ws[0][tx][ty + 16 * r] = Wih[(size_t)(n0 + ty + 16 * r) * KIN_W + tx];
    }
    __syncthreads();
    int buf = 0;
    for (int k0 = 0; k0 < Ev; k0 += 16) {
        float xr[4], wr[4];
        bool more = (k0 + 16 < Ev);
        if (more) {
#pragma unroll
            for (int r = 0; r < 4; r++) {
                xr[r] = emb[(size_t)caprow[r] * Ev + k0 + 16 + tx];
                wr[r] = Wih[(size_t)(n0 + ty + 16 * r) * KIN_W + k0 + 16 + tx];
            }
        }
#pragma unroll
        for (int k = 0; k < 16; k++) {
            ull a0 = *(const ull*)&Xs[buf][k][ty * 4];
            ull a1 = *(const ull*)&Xs[buf][k][ty * 4 + 2];
            float4 bq = *(const float4*)&Ws[buf][k][tx * 4];
            ull bd0 = pk2(bq.x, bq.x), bd1 = pk2(bq.y, bq.y);
            ull bd2 = pk2(bq.z, bq.z), bd3 = pk2(bq.w, bq.w);
            fma2(acc[0][0], a0, bd0); fma2(acc[1][0], a1, bd0);
            fma2(acc[0][1], a0, bd1); fma2(acc[1][1], a1, bd1);
            fma2(acc[0][2], a0, bd2); fma2(acc[1][2], a1, bd2);
            fma2(acc[0][3], a0, bd3); fma2(acc[1][3], a1, bd3);
        }
        if (more) {
#pragma unroll
            for (int r = 0; r < 4; r++) {
                Xs[buf ^ 1][tx][ty + 16 * r] = xr[r];
                Ws[buf ^ 1][tx][ty + 16 * r] = wr[r];
            }
        }
        __syncthreads();
        buf ^= 1;
    }
#pragma unroll
    for (int j = 0; j < 4; j++) {
        int n = n0 + tx * 4 + j;
#pragma unroll
        for (int i = 0; i < 2; i++) {
            float2 v = up2(acc[i][j]);
            int m = m0 + ty * 4 + 2 * i;
            g_gemb[(size_t)m * G4D + n] = v.x;
            g_gemb[(size_t)(m + 1) * G4D + n] = v.y;
        }
    }
}

// ------------------ dh partials: K-split 4 (preamble kernel) -------------------
__global__ void k_dh(const float* __restrict__ decW, const float* __restrict__ decb) {
    __shared__ float Xs[2][16][68];
    __shared__ float Ws[2][16][68];
    int n0 = blockIdx.x * 64;
    int z = blockIdx.y;
    int kbase = z * DHCH;
    int tid = threadIdx.x;
    int tx = tid & 15, ty = tid >> 4;

    ull acc[2][4];
#pragma unroll
    for (int i = 0; i < 2; i++)
#pragma unroll
        for (int j = 0; j < 4; j++) acc[i][j] = 0ull;

#pragma unroll
    for (int r = 0; r < 4; r++) {
        int mm = ty + 16 * r;
        Xs[0][tx][mm] = g_h[mm * Dv + kbase + tx];
        Ws[0][tx][mm] = decW[(size_t)(n0 + mm) * Dv + kbase + tx];
    }
    __syncthreads();
    int buf = 0;
    for (int k0 = 0; k0 < DHCH; k0 += 16) {
        float xr[4], wr[4];
        bool more = (k0 + 16 < DHCH);
        if (more) {
#pragma unroll
            for (int r = 0; r < 4; r++) {
                int mm = ty + 16 * r;
                xr[r] = g_h[mm * Dv + kbase + k0 + 16 + tx];
                wr[r] = decW[(size_t)(n0 + mm) * Dv + kbase + k0 + 16 + tx];
            }
        }
#pragma unroll
        for (int k = 0; k < 16; k++) {
            ull a0 = *(const ull*)&Xs[buf][k][ty * 4];
            ull a1 = *(const ull*)&Xs[buf][k][ty * 4 + 2];
            float4 bq = *(const float4*)&Ws[buf][k][tx * 4];
            ull bd0 = pk2(bq.x, bq.x), bd1 = pk2(bq.y, bq.y);
            ull bd2 = pk2(bq.z, bq.z), bd3 = pk2(bq.w, bq.w);
            fma2(acc[0][0], a0, bd0); fma2(acc[1][0], a1, bd0);
            fma2(acc[0][1], a0, bd1); fma2(acc[1][1], a1, bd1);
            fma2(acc[0][2], a0, bd2); fma2(acc[1][2], a1, bd2);
            fma2(acc[0][3], a0, bd3); fma2(acc[1][3], a1, bd3);
        }
        if (more) {
#pragma unroll
            for (int r = 0; r < 4; r++) {
                int mm = ty + 16 * r;
                Xs[buf ^ 1][tx][mm] = xr[r];
                Ws[buf ^ 1][tx][mm] = wr[r];
            }
        }
        __syncthreads();
        buf ^= 1;
    }
#pragma unroll
    for (int j = 0; j < 4; j++) {
        int n = n0 + tx * 4 + j;
        float bb = (z == 0) ? decb[n] : 0.0f;
#pragma unroll
        for (int i = 0; i < 2; i++) {
            float2 v = up2(acc[i][j]);
            int m = ty * 4 + 2 * i;
            g_dhp[z][m * Av + n] = v.x + bb;
            g_dhp[z][(m + 1) * Av + n] = v.y + bb;
        }
    }
}

// ----------- fused attention: e + softmax + context (one block per b) ----------
__global__ void k_att(const float* __restrict__ fullW, const float* __restrict__ fullb,
                      float* __restrict__ out_alphas, int t) {
    __shared__ float s_dh[Av];
    __shared__ float s_fw[Av];
    __shared__ float s_e[256];
    __shared__ float red[256];
    __shared__ float s_al[256];
    int b = blockIdx.x;
    int tid = threadIdx.x;       // 0..511
    int w = tid >> 5, lane = tid & 31;

    if (tid < Av) {
        int o = b * Av + tid;
        s_dh[tid] = (g_dhp[0][o] + g_dhp[1][o]) + (g_dhp[2][o] + g_dhp[3][o]);
        s_fw[tid] = fullW[tid];
    }
    __syncthreads();

    for (int p = w; p < Pv; p += 16) {
        const float* ep = g_enc_proj + (size_t)(b * Pv + p) * Av;
        float acc = 0.0f;
#pragma unroll
        for (int k = lane; k < Av; k += 32) {
            float v = ep[k] + s_dh[k];
            acc += fmaxf(v, 0.0f) * s_fw[k];
        }
        acc = wsum(acc);
        if (!lane) s_e[p] = acc + fullb[0];
    }
    __syncthreads();

    float v = (tid < Pv) ? s_e[tid] : -3.0e38f;
    if (tid < 256) red[tid] = v;
    __syncthreads();
    for (int s = 128; s; s >>= 1) {
        if (tid < s) red[tid] = fmaxf(red[tid], red[tid + s]);
        __syncthreads();
    }
    float mx = red[0];
    __syncthreads();
    float ex = (tid < Pv) ? expf(v - mx) : 0.0f;
    if (tid < 256) red[tid] = ex;
    __syncthreads();
    for (int s = 128; s; s >>= 1) {
        if (tid < s) red[tid] += red[tid + s];
        __syncthreads();
    }
    float inv = 1.0f / red[0];
    if (tid < Pv) {
        float al = ex * inv;
        s_al[tid] = al;
        out_alphas[((size_t)b * Tv + t) * Pv + tid] = al;
    }
    __syncthreads();

    // context via half2: thread handles e-pairs tid and tid+512 (of 1024 half2)
    const __half2* base2 = (const __half2*)(g_eoT + (size_t)b * Pv * ENCv);
    float a0x = 0.f, a0y = 0.f, a1x = 0.f, a1y = 0.f;
    for (int p = 0; p < Pv; p++) {
        float al = s_al[p];
        const __half2* r2 = base2 + (size_t)p * (ENCv / 2);
        float2 x0 = __half22float2(r2[tid]);
        float2 x1 = __half22float2(r2[tid + 512]);
        a0x += al * x0.x; a0y += al * x0.y;
        a1x += al * x1.x; a1y += al * x1.y;
    }
    __half2* xo = (__half2*)(g_xin16 + (size_t)b * KIN);
    xo[tid]       = __floats2half2_rn(a0x, a0y);
    xo[tid + 512] = __floats2half2_rn(a1x, a1y);
}

// ------------------- gates GEMM via HMMA, K-split 4 -----------------------------
// A = g_xin16 [64][2560], B = g_Wg16 [2048][2560]; partials fp32.
__global__ void k_gates_mma() {
    __shared__ __align__(16) __half As[2][64][40];
    __shared__ __align__(16) __half Bs[2][128][40];
    int n0 = blockIdx.x * 128;     // 16 tiles
    int z = blockIdx.y;            // 4 chunks
    int kbase = z * GCH;
    int tid = threadIdx.x;
    int wid = tid >> 5, lane = tid & 31;
    int wm = wid & 1, wn = wid >> 1;       // 2 x 4 warps; warp tile 32m x 32n
    int g = lane >> 2, tg = lane & 3;

    int arow = tid >> 2;                   // 0..63
    int aseg = (tid & 3) * 8;
    int brow = tid >> 1;                   // 0..127
    int bseg = (tid & 1) * 16;

    const __half* Ag = g_xin16 + (size_t)arow * KIN + kbase + aseg;
    const __half* Bg = g_Wg16 + (size_t)(n0 + brow) * KIN + kbase + bseg;

    float c[2][4][4];
#pragma unroll
    for (int mt = 0; mt < 2; mt++)
#pragma unroll
        for (int nt = 0; nt < 4; nt++)
#pragma unroll
            for (int q = 0; q < 4; q++) c[mt][nt][q] = 0.0f;

    *(uint4*)&As[0][arow][aseg]     = *(const uint4*)(Ag);
    *(uint4*)&Bs[0][brow][bseg]     = *(const uint4*)(Bg);
    *(uint4*)&Bs[0][brow][bseg + 8] = *(const uint4*)(Bg + 8);
    __syncthreads();

    int buf = 0;
    for (int k0 = 0; k0 < GCH; k0 += 32) {
        uint4 pa, pb0, pb1;
        bool more = (k0 + 32 < GCH);
        if (more) {
            pa  = *(const uint4*)(Ag + k0 + 32);
            pb0 = *(const uint4*)(Bg + k0 + 32);
            pb1 = *(const uint4*)(Bg + k0 + 40);
        }
#pragma unroll
        for (int ks = 0; ks < 4; ks++) {
            int kk = ks * 8 + tg * 2;
            unsigned a0[2], a1[2];
#pragma unroll
            for (int mt = 0; mt < 2; mt++) {
                int row = wm * 32 + mt * 16;
                a0[mt] = *(const unsigned*)&As[buf][row + g][kk];
                a1[mt] = *(const unsigned*)&As[buf][row + 8 + g][kk];
            }
#pragma unroll
            for (int nt = 0; nt < 4; nt++) {
                unsigned b0 = *(const unsigned*)&Bs[buf][wn * 32 + nt * 8 + g][kk];
#pragma unroll
                for (int mt = 0; mt < 2; mt++) MMA_K8(c[mt][nt], a0[mt], a1[mt], b0);
            }
        }
        if (more) {
            *(uint4*)&As[buf ^ 1][arow][aseg]     = pa;
            *(uint4*)&Bs[buf ^ 1][brow][bseg]     = pb0;
            *(uint4*)&Bs[buf ^ 1][brow][bseg + 8] = pb1;
        }
        __syncthreads();
        buf ^= 1;
    }

#pragma unroll
    for (int nt = 0; nt < 4; nt++) {
        int n = n0 + wn * 32 + nt * 8 + tg * 2;
#pragma unroll
        for (int mt = 0; mt < 2; mt++) {
            int m = wm * 32 + mt * 16 + g;
            *(float2*)&g_gpart[z][m * G4D + n] = make_float2(c[mt][nt][0], c[mt][nt][1]);
            *(float2*)&g_gpart[z][(m + 8) * G4D + n] = make_float2(c[mt][nt][2], c[mt][nt][3]);
        }
    }
}

// ------------------------------ LSTM pointwise ---------------------------------
__global__ void k_lstm(const float* __restrict__ bih, const float* __restrict__ bhh, int t) {
    int idx = blockIdx.x * blockDim.x + threadIdx.x;
    if (idx >= Bv * Dv) return;
    int b = idx / Dv, d = idx % Dv;
    const float* ge = g_gemb + ((size_t)t * Bv + b) * G4D;
    float gi = bih[d] + bhh[d] + ge[d];
    float gf = bih[Dv + d] + bhh[Dv + d] + ge[Dv + d];
    float gg = bih[2 * Dv + d] + bhh[2 * Dv + d] + ge[2 * Dv + d];
    float go = bih[3 * Dv + d] + bhh[3 * Dv + d] + ge[3 * Dv + d];
    int base = b * G4D + d;
#pragma unroll
    for (int z = 0; z < GZ; z++) {
        gi += g_gpart[z][base];
        gf += g_gpart[z][base + Dv];
        gg += g_gpart[z][base + 2 * Dv];
        go += g_gpart[z][base + 3 * Dv];
    }
    float c = g_c[idx];
    float cn = sigm(gf) * c + sigm(gi) * tanhf(gg);
    float hn = sigm(go) * tanhf(cn);
    g_c[idx] = cn;
    g_h[idx] = hn;
    g_xin16[b * KIN + ENCv + d] = __float2half(hn);
}

// -------------------- fused fc MMA (preds) + dh for next step ------------------
__global__ void k_fcdh(const float* __restrict__ bf,
                       const float* __restrict__ decW, const float* __restrict__ decb,
                       float* __restrict__ preds, int t) {
    __shared__ __align__(16) __half As[2][64][40];
    __shared__ __align__(16) __half Bs[2][128][40];
    __shared__ float Xf[2][16][68];
    __shared__ float Wf2[2][16][68];
    int tid = threadIdx.x;

    if (blockIdx.x < 79) {
        // ------------------------------ fc MMA path ----------------------------
        int n0 = blockIdx.x * 128;
        int wid = tid >> 5, lane = tid & 31;
        int wm = wid & 1, wn = wid >> 1;
        int g = lane >> 2, tg = lane & 3;

        int arow = tid >> 2;
        int aseg = (tid & 3) * 8;
        int brow = tid >> 1;
        int bseg = (tid & 1) * 16;

        const __half* Ag = g_xin16 + (size_t)arow * KIN + ENCv + aseg;  // h slice
        const __half* Bg = g_fcW16 + (size_t)(n0 + brow) * Dv + bseg;

        float c[2][4][4];
#pragma unroll
        for (int mt = 0; mt < 2; mt++)
#pragma unroll
            for (int nt = 0; nt < 4; nt++)
#pragma unroll
                for (int q = 0; q < 4; q++) c[mt][nt][q] = 0.0f;

        *(uint4*)&As[0][arow][aseg]     = *(const uint4*)(Ag);
        *(uint4*)&Bs[0][brow][bseg]     = *(const uint4*)(Bg);
        *(uint4*)&Bs[0][brow][bseg + 8] = *(const uint4*)(Bg + 8);
        __syncthreads();

        int buf = 0;
        for (int k0 = 0; k0 < Dv; k0 += 32) {
            uint4 pa, pb0, pb1;
            bool more = (k0 + 32 < Dv);
            if (more) {
                pa  = *(const uint4*)(Ag + k0 + 32);
                pb0 = *(const uint4*)(Bg + k0 + 32);
                pb1 = *(const uint4*)(Bg + k0 + 40);
            }
#pragma unroll
            for (int ks = 0; ks < 4; ks++) {
                int kk = ks * 8 + tg * 2;
                unsigned a0[2], a1[2];
#pragma unroll
                for (int mt = 0; mt < 2; mt++) {
                    int row = wm * 32 + mt * 16;
                    a0[mt] = *(const unsigned*)&As[buf][row + g][kk];
                    a1[mt] = *(const unsigned*)&As[buf][row + 8 + g][kk];
                }
#pragma unroll
                for (int nt = 0; nt < 4; nt++) {
                    unsigned b0 = *(const unsigned*)&Bs[buf][wn * 32 + nt * 8 + g][kk];
#pragma unroll
                    for (int mt = 0; mt < 2; mt++) MMA_K8(c[mt][nt], a0[mt], a1[mt], b0);
                }
            }
            if (more) {
                *(uint4*)&As[buf ^ 1][arow][aseg]     = pa;
                *(uint4*)&Bs[buf ^ 1][brow][bseg]     = pb0;
                *(uint4*)&Bs[buf ^ 1][brow][bseg + 8] = pb1;
            }
            __syncthreads();
            buf ^= 1;
        }

#pragma unroll
        for (int nt = 0; nt < 4; nt++) {
            int n = n0 + wn * 32 + nt * 8 + tg * 2;
            if (n >= Vv) continue;
            float b0f = bf[n], b1f = bf[n + 1];
#pragma unroll
            for (int mt = 0; mt < 2; mt++) {
                int m = wm * 32 + mt * 16 + g;
                *(float2*)&preds[((size_t)m * Tv + t) * Vv + n] =
                    make_float2(c[mt][nt][0] + b0f, c[mt][nt][1] + b1f);
                *(float2*)&preds[((size_t)(m + 8) * Tv + t) * Vv + n] =
                    make_float2(c[mt][nt][2] + b0f, c[mt][nt][3] + b1f);
            }
        }
    } else {
        // ------------------------------ dh path --------------------------------
        typedef unsigned long long ull2;
        int q = blockIdx.x - 79;        // 0..31
        int n0 = (q & 7) * 64;
        int z = q >> 3;
        int kbase = z * DHCH;
        int tx = tid & 15, ty = tid >> 4;

        ull acc[2][4];
#pragma unroll
        for (int i = 0; i < 2; i++)
#pragma unroll
            for (int j = 0; j < 4; j++) acc[i][j] = 0ull;

#pragma unroll
        for (int r = 0; r < 4; r++) {
            int mm = ty + 16 * r;
            Xf[0][tx][mm] = g_h[mm * Dv + kbase + tx];
            Wf2[0][tx][mm] = decW[(size_t)(n0 + mm) * Dv + kbase + tx];
        }
        __syncthreads();
        int buf = 0;
        for (int k0 = 0; k0 < DHCH; k0 += 16) {
            float xr[4], wr[4];
            bool more = (k0 + 16 < DHCH);
            if (more) {
#pragma unroll
                for (int r = 0; r < 4; r++) {
                    int mm = ty + 16 * r;
                    xr[r] = g_h[mm * Dv + kbase + k0 + 16 + tx];
                    wr[r] = decW[(size_t)(n0 + mm) * Dv + kbase + k0 + 16 + tx];
                }
            }
#pragma unroll
            for (int k = 0; k < 16; k++) {
                ull a0 = *(const ull*)&Xf[buf][k][ty * 4];
                ull a1 = *(const ull*)&Xf[buf][k][ty * 4 + 2];
                float4 bq = *(const float4*)&Wf2[buf][k][tx * 4];
                ull bd0 = pk2(bq.x, bq.x), bd1 = pk2(bq.y, bq.y);
                ull bd2 = pk2(bq.z, bq.z), bd3 = pk2(bq.w, bq.w);
                fma2(acc[0][0], a0, bd0); fma2(acc[1][0], a1, bd0);
                fma2(acc[0][1], a0, bd1); fma2(acc[1][1], a1, bd1);
                fma2(acc[0][2], a0, bd2); fma2(acc[1][2], a1, bd2);
                fma2(acc[0][3], a0, bd3); fma2(acc[1][3], a1, bd3);
            }
            if (more) {
#pragma unroll
                for (int r = 0; r < 4; r++) {
                    int mm = ty + 16 * r;
                    Xf[buf ^ 1][tx][mm] = xr[r];
                    Wf2[buf ^ 1][tx][mm] = wr[r];
                }
            }
            __syncthreads();
            buf ^= 1;
        }
#pragma unroll
        for (int j = 0; j < 4; j++) {
            int n = n0 + tx * 4 + j;
            float bb = (z == 0) ? decb[n] : 0.0f;
#pragma unroll
            for (int i = 0; i < 2; i++) {
                float2 v = up2(acc[i][j]);
                int m = ty * 4 + 2 * i;
                g_dhp[z][m * Av + n] = v.x + bb;
                g_dhp[z][(m + 1) * Av + n] = v.y + bb;
            }
        }
    }
}

// --------------------------------- launcher ------------------------------------
extern "C" void kernel_launch(void* const* d_in, const int* in_sizes, int n_in,
                              void* d_out, int out_size) {
    const float* eo    = (const float*)d_in[0];
    const int*   caps  = (const int*)d_in[1];
    const float* emb   = (const float*)d_in[3];
    const float* encW  = (const float*)d_in[4];
    const float* encb  = (const float*)d_in[5];
    const float* decW  = (const float*)d_in[6];
    const float* decb  = (const float*)d_in[7];
    const float* fullW = (const float*)d_in[8];
    const float* fullb = (const float*)d_in[9];
    const float* ihW   = (const float*)d_in[10];
    const float* ihb   = (const float*)d_in[11];
    const float* icW   = (const float*)d_in[12];
    const float* icb   = (const float*)d_in[13];
    const float* Wih   = (const float*)d_in[14];
    const float* bih   = (const float*)d_in[15];
    const float* Whh   = (const float*)d_in[16];
    const float* bhh   = (const float*)d_in[17];
    const float* fcW   = (const float*)d_in[18];
    const float* fcb   = (const float*)d_in[19];

    float* preds  = (float*)d_out;
    float* alphas = preds + (size_t)Bv * Tv * Vv;

    k_zero_tail<<<(Bv * Vv + Bv * Pv + 255) / 256, 256>>>(preds, alphas);
    k_cvtT<<<dim3(ENCv / 32, (Pv + 31) / 32, Bv), dim3(32, 8)>>>(eo);
    k_cvtW<<<(Av * ENCv / 4 + 255) / 256, 256>>>(encW);
    k_cvt_Wg<<<(G4D * KIN / 2 + 255) / 256, 256>>>(Wih, Whh);
    k_cvt_fcW<<<(NFCPAD * Dv / 2 + 255) / 256, 256>>>(fcW);
    k_mean<<<(Bv * ENCv * 32 + 255) / 256, 256>>>(eo);
    k_init<<<(2 * Bv * Dv * 32 + 255) / 256, 256>>>(ihW, ihb, icW, icb);
    k_embW<<<dim3(32, 31), 256>>>(caps, emb, Wih);
    k_encproj_mma<<<dim3(98, 4), 256>>>(encb);
    k_dh<<<dim3(8, DHZ), 256>>>(decW, decb);

    for (int t = 0; t < NSTEP; t++) {
        k_att<<<Bv, 512>>>(fullW, fullb, alphas, t);
        k_gates_mma<<<dim3(16, GZ), 256>>>();
        k_lstm<<<(Bv * Dv + 255) / 256, 256>>>(bih, bhh, t);
        k_fcdh<<<111, 256>>>(fcb, decW, decb, preds, t);
    }
}

// round 9
// speedup vs baseline: 4.6529x; 1.0578x over previous
#include <cuda_runtime.h>
#include <cuda_fp16.h>
#include <math.h>

#define Bv    64
#define Pv    196
#define ENCv  2048
#define Ev    512
#define Dv    512
#define Av    512
#define Vv    10000
#define Tv    32
#define NSTEP 31
#define G4D   2048          // 4*D
#define KIN   2560          // ENC + D (ctx | h)
#define KIN_W 2560          // Wih row stride (E+ENC)
#define GZ    4             // gates K-split
#define GCH   640           // KIN / GZ
#define DHZ   4             // dh K-split
#define DHCH  128           // Dv / DHZ
#define NFCPAD 10112        // fc rows padded to 79*128
#define MEMB  1984          // NSTEP*Bv

typedef unsigned long long ull;

// ------------------------- scratch (static device globals) -------------------
__device__ float g_enc_proj[Bv * Pv * Av];        // 25.7 MB
__device__ __half g_eoT[Bv * Pv * ENCv];          // 51.4 MB fp16 transpose [b][p][e]
__device__ __half g_encW16[Av * ENCv];            // 2 MB
__device__ __half g_Wg16[G4D * KIN];              // 10.5 MB  [Wih_ctx | Whh]
__device__ __half g_fcW16[NFCPAD * Dv];           // 10.3 MB
__device__ __half g_embA16[2048 * Ev];            // 2 MB gathered emb rows (fp16)
__device__ __half g_Wihe16[G4D * Ev];             // 2 MB Wih embedding slice (fp16)
__device__ __half g_xin16[Bv * KIN];              // fp16 [ctx | h]
__device__ float g_mean[Bv * ENCv];
__device__ float g_h[Bv * Dv];
__device__ float g_c[Bv * Dv];
__device__ float g_dhp[DHZ][Bv * Av];
__device__ float g_e[Bv * Pv];
__device__ float g_gpart[GZ][Bv * G4D];
__device__ float g_gemb[NSTEP * Bv * G4D];        // 16.2 MB

// ------------------------------- helpers -------------------------------------
__device__ __forceinline__ ull pk2(float lo, float hi) {
    ull r; asm("mov.b64 %0, {%1, %2};" : "=l"(r) : "f"(lo), "f"(hi)); return r;
}
__device__ __forceinline__ void fma2(ull& d, ull a, ull b) {
    asm("fma.rn.f32x2 %0, %1, %2, %0;" : "+l"(d) : "l"(a), "l"(b));
}
__device__ __forceinline__ float2 up2(ull v) {
    float lo, hi; asm("mov.b64 {%0, %1}, %2;" : "=f"(lo), "=f"(hi) : "l"(v));
    return make_float2(lo, hi);
}
__device__ __forceinline__ float wsum(float v) {
#pragma unroll
    for (int o = 16; o; o >>= 1) v += __shfl_down_sync(0xffffffffu, v, o);
    return v;
}
__device__ __forceinline__ float sigm(float x) { return 1.0f / (1.0f + expf(-x)); }

#define MMA_K8(c, a0, a1, b0) \
    asm volatile("mma.sync.aligned.m16n8k8.row.col.f32.f16.f16.f32 " \
                 "{%0,%1,%2,%3}, {%4,%5}, {%6}, {%0,%1,%2,%3};" \
                 : "+f"((c)[0]), "+f"((c)[1]), "+f"((c)[2]), "+f"((c)[3]) \
                 : "r"(a0), "r"(a1), "r"(b0))

// -------------------- zero last timestep + g_mean ------------------------------
__global__ void k_zero_tail(float* __restrict__ preds, float* __restrict__ alphas) {
    int idx = blockIdx.x * blockDim.x + threadIdx.x;
    if (idx < Bv * Vv) {
        int b = idx / Vv, v = idx % Vv;
        preds[((size_t)b * Tv + (Tv - 1)) * Vv + v] = 0.0f;
    } else if (idx < Bv * Vv + Bv * Pv) {
        int r = idx - Bv * Vv;
        int b = r / Pv, p = r % Pv;
        alphas[((size_t)b * Tv + (Tv - 1)) * Pv + p] = 0.0f;
    } else {
        int r = idx - Bv * Vv - Bv * Pv;
        if (r < Bv * ENCv) g_mean[r] = 0.0f;
    }
}

// ------------- transpose eo -> g_eoT fp16 [b][p][e], + mean partials -----------
__global__ void k_cvtT(const float* __restrict__ eo) {
    __shared__ float tile[32][33];
    int b = blockIdx.z;
    int e0 = blockIdx.x * 32;
    int p0 = blockIdx.y * 32;
    int tx = threadIdx.x, ty = threadIdx.y;
#pragma unroll
    for (int r = 0; r < 4; r++) {
        int e = e0 + ty + 8 * r;
        int p = p0 + tx;
        tile[ty + 8 * r][tx] = (p < Pv) ? eo[((size_t)b * ENCv + e) * Pv + p] : 0.0f;
    }
    __syncthreads();
#pragma unroll
    for (int r = 0; r < 4; r++) {
        int p = p0 + ty + 8 * r;
        int e = e0 + tx;
        if (p < Pv)
            g_eoT[((size_t)b * Pv + p) * ENCv + e] = __float2half(tile[tx][ty + 8 * r]);
    }
    // mean partial sums (warp = fixed ty, lanes over tx = p direction)
#pragma unroll
    for (int r = 0; r < 4; r++) {
        float v = wsum(tile[ty + 8 * r][tx]);
        if (tx == 0) atomicAdd(&g_mean[b * ENCv + e0 + ty + 8 * r], v);
    }
}

// -------------------------- convert encW -> fp16 -------------------------------
__global__ void k_cvtW(const float* __restrict__ W) {
    int i = blockIdx.x * blockDim.x + threadIdx.x;
    const int N4 = Av * ENCv / 4;
    if (i >= N4) return;
    float4 v = ((const float4*)W)[i];
    __half2* out = (__half2*)g_encW16;
    out[i * 2]     = __floats2half2_rn(v.x, v.y);
    out[i * 2 + 1] = __floats2half2_rn(v.z, v.w);
}

// ------------------- build g_Wg16 = [Wih_ctx | Whh] fp16 -----------------------
__global__ void k_cvt_Wg(const float* __restrict__ Wih, const float* __restrict__ Whh) {
    int i = blockIdx.x * blockDim.x + threadIdx.x;
    const int N2 = G4D * KIN / 2;
    if (i >= N2) return;
    int n = i / (KIN / 2);
    int k = (i % (KIN / 2)) * 2;
    float v0, v1;
    if (k < ENCv) {
        v0 = Wih[(size_t)n * KIN_W + Ev + k];
        v1 = Wih[(size_t)n * KIN_W + Ev + k + 1];
    } else {
        v0 = Whh[(size_t)n * Dv + (k - ENCv)];
        v1 = Whh[(size_t)n * Dv + (k - ENCv) + 1];
    }
    ((__half2*)g_Wg16)[i] = __floats2half2_rn(v0, v1);
}

// ------------------------ build g_fcW16 (padded) fp16 --------------------------
__global__ void k_cvt_fcW(const float* __restrict__ Wf) {
    int i = blockIdx.x * blockDim.x + threadIdx.x;
    const int N2 = NFCPAD * Dv / 2;
    if (i >= N2) return;
    int n = i / (Dv / 2);
    int k = (i % (Dv / 2)) * 2;
    float v0 = 0.f, v1 = 0.f;
    if (n < Vv) {
        v0 = Wf[(size_t)n * Dv + k];
        v1 = Wf[(size_t)n * Dv + k + 1];
    }
    ((__half2*)g_fcW16)[i] = __floats2half2_rn(v0, v1);
}

// ------------------- gather emb rows (per step) -> fp16 ------------------------
__global__ void k_cvt_emb(const int* __restrict__ caps, const float* __restrict__ emb) {
    int i = blockIdx.x * blockDim.x + threadIdx.x;
    const int N2 = 2048 * (Ev / 2);
    if (i >= N2) return;
    int m = i / (Ev / 2);
    int k = (i % (Ev / 2)) * 2;
    float v0 = 0.f, v1 = 0.f;
    if (m < MEMB) {
        int b = m & 63, t = m >> 6;
        int cap = caps[b * Tv + t];
        v0 = emb[(size_t)cap * Ev + k];
        v1 = emb[(size_t)cap * Ev + k + 1];
    }
    ((__half2*)g_embA16)[i] = __floats2half2_rn(v0, v1);
}

// ---------------------- Wih embedding slice -> fp16 ----------------------------
__global__ void k_cvt_Wihe(const float* __restrict__ Wih) {
    int i = blockIdx.x * blockDim.x + threadIdx.x;
    const int N2 = G4D * (Ev / 2);
    if (i >= N2) return;
    int n = i / (Ev / 2);
    int k = (i % (Ev / 2)) * 2;
    ((__half2*)g_Wihe16)[i] =
        __floats2half2_rn(Wih[(size_t)n * KIN_W + k], Wih[(size_t)n * KIN_W + k + 1]);
}

// -------------------------------- h0 / c0 -------------------------------------
__global__ void k_init(const float* __restrict__ Wh, const float* __restrict__ bh,
                       const float* __restrict__ Wc, const float* __restrict__ bc) {
    int gw = (blockIdx.x * blockDim.x + threadIdx.x) >> 5;
    int lane = threadIdx.x & 31;
    if (gw >= 2 * Bv * Dv) return;
    int sel = gw >= Bv * Dv;
    int r = gw - sel * Bv * Dv;
    int b = r / Dv, d = r % Dv;
    const float* W = sel ? Wc : Wh;
    const float* mn = g_mean + (size_t)b * ENCv;   // holds SUMS over p
    const float* wr = W + (size_t)d * ENCv;
    float acc = 0.0f;
    for (int k = lane; k < ENCv; k += 32) acc += mn[k] * wr[k];
    acc = wsum(acc);
    if (!lane) {
        float v = acc * (1.0f / (float)Pv) + (sel ? bc : bh)[d];
        if (sel) g_c[r] = v;
        else { g_h[r] = v; g_xin16[b * KIN + ENCv + d] = __float2half(v); }
    }
}

// -------------------- enc_proj GEMM via HMMA (m16n8k8) -------------------------
__global__ __launch_bounds__(256, 2)
void k_encproj_mma(const float* __restrict__ bias) {
    __shared__ __align__(16) __half As[2][128][40];
    __shared__ __align__(16) __half Bs[2][128][40];
    int m0 = blockIdx.x * 128;
    int n0 = blockIdx.y * 128;
    int tid = threadIdx.x;
    int wid = tid >> 5, lane = tid & 31;
    int wm = wid & 3, wn = wid >> 2;
    int g = lane >> 2, tg = lane & 3;

    int lrow = tid >> 1;
    int lseg = (tid & 1) * 16;

    const __half* Ag = g_eoT + (size_t)(m0 + lrow) * ENCv + lseg;
    const __half* Bg = g_encW16 + (size_t)(n0 + lrow) * ENCv + lseg;

    float c[2][8][4];
#pragma unroll
    for (int mt = 0; mt < 2; mt++)
#pragma unroll
        for (int nt = 0; nt < 8; nt++)
#pragma unroll
            for (int q = 0; q < 4; q++) c[mt][nt][q] = 0.0f;

    *(uint4*)&As[0][lrow][lseg]     = *(const uint4*)(Ag);
    *(uint4*)&As[0][lrow][lseg + 8] = *(const uint4*)(Ag + 8);
    *(uint4*)&Bs[0][lrow][lseg]     = *(const uint4*)(Bg);
    *(uint4*)&Bs[0][lrow][lseg + 8] = *(const uint4*)(Bg + 8);
    __syncthreads();

    int buf = 0;
    for (int k0 = 0; k0 < ENCv; k0 += 32) {
        uint4 pa0, pa1, pb0, pb1;
        bool more = (k0 + 32 < ENCv);
        if (more) {
            pa0 = *(const uint4*)(Ag + k0 + 32);
            pa1 = *(const uint4*)(Ag + k0 + 40);
            pb0 = *(const uint4*)(Bg + k0 + 32);
            pb1 = *(const uint4*)(Bg + k0 + 40);
        }
#pragma unroll
        for (int ks = 0; ks < 4; ks++) {
            int kk = ks * 8 + tg * 2;
            unsigned a0[2], a1[2];
#pragma unroll
            for (int mt = 0; mt < 2; mt++) {
                int row = wm * 32 + mt * 16;
                a0[mt] = *(const unsigned*)&As[buf][row + g][kk];
                a1[mt] = *(const unsigned*)&As[buf][row + 8 + g][kk];
            }
#pragma unroll
            for (int nt = 0; nt < 8; nt++) {
                unsigned b0 = *(const unsigned*)&Bs[buf][wn * 64 + nt * 8 + g][kk];
#pragma unroll
                for (int mt = 0; mt < 2; mt++) MMA_K8(c[mt][nt], a0[mt], a1[mt], b0);
            }
        }
        if (more) {
            *(uint4*)&As[buf ^ 1][lrow][lseg]     = pa0;
            *(uint4*)&As[buf ^ 1][lrow][lseg + 8] = pa1;
            *(uint4*)&Bs[buf ^ 1][lrow][lseg]     = pb0;
            *(uint4*)&Bs[buf ^ 1][lrow][lseg + 8] = pb1;
        }
        __syncthreads();
        buf ^= 1;
    }

#pragma unroll
    for (int nt = 0; nt < 8; nt++) {
        int n = n0 + wn * 64 + nt * 8 + tg * 2;
        float b0f = bias[n], b1f = bias[n + 1];
#pragma unroll
        for (int mt = 0; mt < 2; mt++) {
            int m = m0 + wm * 32 + mt * 16 + g;
            *(float2*)&g_enc_proj[(size_t)m * Av + n] =
                make_float2(c[mt][nt][0] + b0f, c[mt][nt][1] + b1f);
            *(float2*)&g_enc_proj[(size_t)(m + 8) * Av + n] =
                make_float2(c[mt][nt][2] + b0f, c[mt][nt][3] + b1f);
        }
    }
}

// ------------------ g_gemb = embA @ Wihe.T via HMMA ----------------------------
__global__ __launch_bounds__(256, 2)
void k_embW_mma() {
    __shared__ __align__(16) __half As[2][128][40];
    __shared__ __align__(16) __half Bs[2][128][40];
    int m0 = blockIdx.x * 128;     // 16 tiles (2048 padded)
    int n0 = blockIdx.y * 128;     // 16 tiles
    int tid = threadIdx.x;
    int wid = tid >> 5, lane = tid & 31;
    int wm = wid & 3, wn = wid >> 2;
    int g = lane >> 2, tg = lane & 3;

    int lrow = tid >> 1;
    int lseg = (tid & 1) * 16;

    const __half* Ag = g_embA16 + (size_t)(m0 + lrow) * Ev + lseg;
    const __half* Bg = g_Wihe16 + (size_t)(n0 + lrow) * Ev + lseg;

    float c[2][8][4];
#pragma unroll
    for (int mt = 0; mt < 2; mt++)
#pragma unroll
        for (int nt = 0; nt < 8; nt++)
#pragma unroll
            for (int q = 0; q < 4; q++) c[mt][nt][q] = 0.0f;

    *(uint4*)&As[0][lrow][lseg]     = *(const uint4*)(Ag);
    *(uint4*)&As[0][lrow][lseg + 8] = *(const uint4*)(Ag + 8);
    *(uint4*)&Bs[0][lrow][lseg]     = *(const uint4*)(Bg);
    *(uint4*)&Bs[0][lrow][lseg + 8] = *(const uint4*)(Bg + 8);
    __syncthreads();

    int buf = 0;
    for (int k0 = 0; k0 < Ev; k0 += 32) {
        uint4 pa0, pa1, pb0, pb1;
        bool more = (k0 + 32 < Ev);
        if (more) {
            pa0 = *(const uint4*)(Ag + k0 + 32);
            pa1 = *(const uint4*)(Ag + k0 + 40);
            pb0 = *(const uint4*)(Bg + k0 + 32);
            pb1 = *(const uint4*)(Bg + k0 + 40);
        }
#pragma unroll
        for (int ks = 0; ks < 4; ks++) {
            int kk = ks * 8 + tg * 2;
            unsigned a0[2], a1[2];
#pragma unroll
            for (int mt = 0; mt < 2; mt++) {
                int row = wm * 32 + mt * 16;
                a0[mt] = *(const unsigned*)&As[buf][row + g][kk];
                a1[mt] = *(const unsigned*)&As[buf][row + 8 + g][kk];
            }
#pragma unroll
            for (int nt = 0; nt < 8; nt++) {
                unsigned b0 = *(const unsigned*)&Bs[buf][wn * 64 + nt * 8 + g][kk];
#pragma unroll
                for (int mt = 0; mt < 2; mt++) MMA_K8(c[mt][nt], a0[mt], a1[mt], b0);
            }
        }
        if (more) {
            *(uint4*)&As[buf ^ 1][lrow][lseg]     = pa0;
            *(uint4*)&As[buf ^ 1][lrow][lseg + 8] = pa1;
            *(uint4*)&Bs[buf ^ 1][lrow][lseg]     = pb0;
            *(uint4*)&Bs[buf ^ 1][lrow][lseg + 8] = pb1;
        }
        __syncthreads();
        buf ^= 1;
    }

#pragma unroll
    for (int nt = 0; nt < 8; nt++) {
        int n = n0 + wn * 64 + nt * 8 + tg * 2;
#pragma unroll
        for (int mt = 0; mt < 2; mt++) {
            int m = m0 + wm * 32 + mt * 16 + g;
            if (m < MEMB)
                *(float2*)&g_gemb[(size_t)m * G4D + n] =
                    make_float2(c[mt][nt][0], c[mt][nt][1]);
            if (m + 8 < MEMB)
                *(float2*)&g_gemb[(size_t)(m + 8) * G4D + n] =
                    make_float2(c[mt][nt][2], c[mt][nt][3]);
        }
    }
}

// ------------------ dh partials: K-split 4 (preamble kernel) -------------------
__global__ void k_dh(const float* __restrict__ decW, const float* __restrict__ decb) {
    __shared__ float Xs[2][16][68];
    __shared__ float Ws[2][16][68];
    int n0 = blockIdx.x * 64;
    int z = blockIdx.y;
    int kbase = z * DHCH;
    int tid = threadIdx.x;
    int tx = tid & 15, ty = tid >> 4;

    ull acc[2][4];
#pragma unroll
    for (int i = 0; i < 2; i++)
#pragma unroll
        for (int j = 0; j < 4; j++) acc[i][j] = 0ull;

#pragma unroll
    for (int r = 0; r < 4; r++) {
        int mm = ty + 16 * r;
        Xs[0][tx][mm] = g_h[mm * Dv + kbase + tx];
        Ws[0][tx][mm] = decW[(size_t)(n0 + mm) * Dv + kbase + tx];
    }
    __syncthreads();
    int buf = 0;
    for (int k0 = 0; k0 < DHCH; k0 += 16) {
        float xr[4], wr[4];
        bool more = (k0 + 16 < DHCH);
        if (more) {
#pragma unroll
            for (int r = 0; r < 4; r++) {
                int mm = ty + 16 * r;
                xr[r] = g_h[mm * Dv + kbase + k0 + 16 + tx];
                wr[r] = decW[(size_t)(n0 + mm) * Dv + kbase + k0 + 16 + tx];
            }
        }
#pragma unroll
        for (int k = 0; k < 16; k++) {
            ull a0 = *(const ull*)&Xs[buf][k][ty * 4];
            ull a1 = *(const ull*)&Xs[buf][k][ty * 4 + 2];
            float4 bq = *(const float4*)&Ws[buf][k][tx * 4];
            ull bd0 = pk2(bq.x, bq.x), bd1 = pk2(bq.y, bq.y);
            ull bd2 = pk2(bq.z, bq.z), bd3 = pk2(bq.w, bq.w);
            fma2(acc[0][0], a0, bd0); fma2(acc[1][0], a1, bd0);
            fma2(acc[0][1], a0, bd1); fma2(acc[1][1], a1, bd1);
            fma2(acc[0][2], a0, bd2); fma2(acc[1][2], a1, bd2);
            fma2(acc[0][3], a0, bd3); fma2(acc[1][3], a1, bd3);
        }
        if (more) {
#pragma unroll
            for (int r = 0; r < 4; r++) {
                int mm = ty + 16 * r;
                Xs[buf ^ 1][tx][mm] = xr[r];
                Ws[buf ^ 1][tx][mm] = wr[r];
            }
        }
        __syncthreads();
        buf ^= 1;
    }
#pragma unroll
    for (int j = 0; j < 4; j++) {
        int n = n0 + tx * 4 + j;
        float bb = (z == 0) ? decb[n] : 0.0f;
#pragma unroll
        for (int i = 0; i < 2; i++) {
            float2 v = up2(acc[i][j]);
            int m = ty * 4 + 2 * i;
            g_dhp[z][m * Av + n] = v.x + bb;
            g_dhp[z][(m + 1) * Av + n] = v.y + bb;
        }
    }
}

// ----------------------- e scores: grid (25, 64) -------------------------------
__global__ void k_e(const float* __restrict__ fullW, const float* __restrict__ fullb) {
    __shared__ float s_dh[Av];
    __shared__ float s_fw[Av];
    int b = blockIdx.y;
    int tid = threadIdx.x;
    for (int i = tid; i < Av; i += 256) {
        int o = b * Av + i;
        s_dh[i] = (g_dhp[0][o] + g_dhp[1][o]) + (g_dhp[2][o] + g_dhp[3][o]);
        s_fw[i] = fullW[i];
    }
    __syncthreads();
    int w = tid >> 5, lane = tid & 31;
    int p = blockIdx.x * 8 + w;
    if (p >= Pv) return;
    const float* ep = g_enc_proj + (size_t)(b * Pv + p) * Av;
    float acc = 0.0f;
#pragma unroll
    for (int k = lane; k < Av; k += 32) {
        float v = ep[k] + s_dh[k];
        acc += fmaxf(v, 0.0f) * s_fw[k];
    }
    acc = wsum(acc);
    if (!lane) g_e[b * Pv + p] = acc + fullb[0];
}

// ------------- softmax (redundant) + context: grid (4, 64) ---------------------
__global__ void k_ctx(float* __restrict__ out_alphas, int t) {
    __shared__ float red[256];
    __shared__ float s_al[Pv];
    int b = blockIdx.y;
    int tid = threadIdx.x;

    float v = (tid < Pv) ? g_e[b * Pv + tid] : -3.0e38f;
    red[tid] = v; __syncthreads();
    for (int s = 128; s; s >>= 1) {
        if (tid < s) red[tid] = fmaxf(red[tid], red[tid + s]);
        __syncthreads();
    }
    float mx = red[0]; __syncthreads();
    float ex = (tid < Pv) ? expf(v - mx) : 0.0f;
    red[tid] = ex; __syncthreads();
    for (int s = 128; s; s >>= 1) {
        if (tid < s) red[tid] += red[tid + s];
        __syncthreads();
    }
    float inv = 1.0f / red[0];
    if (tid < Pv) {
        float al = ex * inv;
        s_al[tid] = al;
        if (blockIdx.x == 0)
            out_alphas[((size_t)b * Tv + t) * Pv + tid] = al;
    }
    __syncthreads();

    int c = blockIdx.x * 256 + tid;   // half2 column 0..1023
    const __half2* base2 = (const __half2*)(g_eoT + (size_t)b * Pv * ENCv);
    float ax = 0.f, ay = 0.f;
#pragma unroll 4
    for (int p = 0; p < Pv; p++) {
        float al = s_al[p];
        float2 x = __half22float2(base2[(size_t)p * (ENCv / 2) + c]);
        ax += al * x.x; ay += al * x.y;
    }
    ((__half2*)(g_xin16 + (size_t)b * KIN))[c] = __floats2half2_rn(ax, ay);
}

// ------------------- gates GEMM via HMMA, K-split 4 -----------------------------
__global__ void k_gates_mma() {
    __shared__ __align__(16) __half As[2][64][40];
    __shared__ __align__(16) __half Bs[2][128][40];
    int n0 = blockIdx.x * 128;
    int z = blockIdx.y;
    int kbase = z * GCH;
    int tid = threadIdx.x;
    int wid = tid >> 5, lane = tid & 31;
    int wm = wid & 1, wn = wid >> 1;
    int g = lane >> 2, tg = lane & 3;

    int arow = tid >> 2;
    int aseg = (tid & 3) * 8;
    int brow = tid >> 1;
    int bseg = (tid & 1) * 16;

    const __half* Ag = g_xin16 + (size_t)arow * KIN + kbase + aseg;
    const __half* Bg = g_Wg16 + (size_t)(n0 + brow) * KIN + kbase + bseg;

    float c[2][4][4];
#pragma unroll
    for (int mt = 0; mt < 2; mt++)
#pragma unroll
        for (int nt = 0; nt < 4; nt++)
#pragma unroll
            for (int q = 0; q < 4; q++) c[mt][nt][q] = 0.0f;

    *(uint4*)&As[0][arow][aseg]     = *(const uint4*)(Ag);
    *(uint4*)&Bs[0][brow][bseg]     = *(const uint4*)(Bg);
    *(uint4*)&Bs[0][brow][bseg + 8] = *(const uint4*)(Bg + 8);
    __syncthreads();

    int buf = 0;
    for (int k0 = 0; k0 < GCH; k0 += 32) {
        uint4 pa, pb0, pb1;
        bool more = (k0 + 32 < GCH);
        if (more) {
            pa  = *(const uint4*)(Ag + k0 + 32);
            pb0 = *(const uint4*)(Bg + k0 + 32);
            pb1 = *(const uint4*)(Bg + k0 + 40);
        }
#pragma unroll
        for (int ks = 0; ks < 4; ks++) {
            int kk = ks * 8 + tg * 2;
            unsigned a0[2], a1[2];
#pragma unroll
            for (int mt = 0; mt < 2; mt++) {
                int row = wm * 32 + mt * 16;
                a0[mt] = *(const unsigned*)&As[buf][row + g][kk];
                a1[mt] = *(const unsigned*)&As[buf][row + 8 + g][kk];
            }
#pragma unroll
            for (int nt = 0; nt < 4; nt++) {
                unsigned b0 = *(const unsigned*)&Bs[buf][wn * 32 + nt * 8 + g][kk];
#pragma unroll
                for (int mt = 0; mt < 2; mt++) MMA_K8(c[mt][nt], a0[mt], a1[mt], b0);
            }
        }
        if (more) {
            *(uint4*)&As[buf ^ 1][arow][aseg]     = pa;
            *(uint4*)&Bs[buf ^ 1][brow][bseg]     = pb0;
            *(uint4*)&Bs[buf ^ 1][brow][bseg + 8] = pb1;
        }
        __syncthreads();
        buf ^= 1;
    }

#pragma unroll
    for (int nt = 0; nt < 4; nt++) {
        int n = n0 + wn * 32 + nt * 8 + tg * 2;
#pragma unroll
        for (int mt = 0; mt < 2; mt++) {
            int m = wm * 32 + mt * 16 + g;
            *(float2*)&g_gpart[z][m * G4D + n] = make_float2(c[mt][nt][0], c[mt][nt][1]);
            *(float2*)&g_gpart[z][(m + 8) * G4D + n] = make_float2(c[mt][nt][2], c[mt][nt][3]);
        }
    }
}

// ------------------------------ LSTM pointwise ---------------------------------
__global__ void k_lstm(const float* __restrict__ bih, const float* __restrict__ bhh, int t) {
    int idx = blockIdx.x * blockDim.x + threadIdx.x;
    if (idx >= Bv * Dv) return;
    int b = idx / Dv, d = idx % Dv;
    const float* ge = g_gemb + ((size_t)t * Bv + b) * G4D;
    float gi = bih[d] + bhh[d] + ge[d];
    float gf = bih[Dv + d] + bhh[Dv + d] + ge[Dv + d];
    float gg = bih[2 * Dv + d] + bhh[2 * Dv + d] + ge[2 * Dv + d];
    float go = bih[3 * Dv + d] + bhh[3 * Dv + d] + ge[3 * Dv + d];
    int base = b * G4D + d;
#pragma unroll
    for (int z = 0; z < GZ; z++) {
        gi += g_gpart[z][base];
        gf += g_gpart[z][base + Dv];
        gg += g_gpart[z][base + 2 * Dv];
        go += g_gpart[z][base + 3 * Dv];
    }
    float c = g_c[idx];
    float cn = sigm(gf) * c + sigm(gi) * tanhf(gg);
    float hn = sigm(go) * tanhf(cn);
    g_c[idx] = cn;
    g_h[idx] = hn;
    g_xin16[b * KIN + ENCv + d] = __float2half(hn);
}

// -------------------- fused fc MMA (preds) + dh for next step ------------------
__global__ void k_fcdh(const float* __restrict__ bf,
                       const float* __restrict__ decW, const float* __restrict__ decb,
                       float* __restrict__ preds, int t) {
    __shared__ __align__(16) __half As[2][64][40];
    __shared__ __align__(16) __half Bs[2][128][40];
    __shared__ float Xf[2][16][68];
    __shared__ float Wf2[2][16][68];
    int tid = threadIdx.x;

    if (blockIdx.x < 79) {
        int n0 = blockIdx.x * 128;
        int wid = tid >> 5, lane = tid & 31;
        int wm = wid & 1, wn = wid >> 1;
        int g = lane >> 2, tg = lane & 3;

        int arow = tid >> 2;
        int aseg = (tid & 3) * 8;
        int brow = tid >> 1;
        int bseg = (tid & 1) * 16;

        const __half* Ag = g_xin16 + (size_t)arow * KIN + ENCv + aseg;
        const __half* Bg = g_fcW16 + (size_t)(n0 + brow) * Dv + bseg;

        float c[2][4][4];
#pragma unroll
        for (int mt = 0; mt < 2; mt++)
#pragma unroll
            for (int nt = 0; nt < 4; nt++)
#pragma unroll
                for (int q = 0; q < 4; q++) c[mt][nt][q] = 0.0f;

        *(uint4*)&As[0][arow][aseg]     = *(const uint4*)(Ag);
        *(uint4*)&Bs[0][brow][bseg]     = *(const uint4*)(Bg);
        *(uint4*)&Bs[0][brow][bseg + 8] = *(const uint4*)(Bg + 8);
        __syncthreads();

        int buf = 0;
        for (int k0 = 0; k0 < Dv; k0 += 32) {
            uint4 pa, pb0, pb1;
            bool more = (k0 + 32 < Dv);
            if (more) {
                pa  = *(const uint4*)(Ag + k0 + 32);
                pb0 = *(const uint4*)(Bg + k0 + 32);
                pb1 = *(const uint4*)(Bg + k0 + 40);
            }
#pragma unroll
            for (int ks = 0; ks < 4; ks++) {
                int kk = ks * 8 + tg * 2;
                unsigned a0[2], a1[2];
#pragma unroll
                for (int mt = 0; mt < 2; mt++) {
                    int row = wm * 32 + mt * 16;
                    a0[mt] = *(const unsigned*)&As[buf][row + g][kk];
                    a1[mt] = *(const unsigned*)&As[buf][row + 8 + g][kk];
                }
#pragma unroll
                for (int nt = 0; nt < 4; nt++) {
                    unsigned b0 = *(const unsigned*)&Bs[buf][wn * 32 + nt * 8 + g][kk];
#pragma unroll
                    for (int mt = 0; mt < 2; mt++) MMA_K8(c[mt][nt], a0[mt], a1[mt], b0);
                }
            }
            if (more) {
                *(uint4*)&As[buf ^ 1][arow][aseg]     = pa;
                *(uint4*)&Bs[buf ^ 1][brow][bseg]     = pb0;
                *(uint4*)&Bs[buf ^ 1][brow][bseg + 8] = pb1;
            }
            __syncthreads();
            buf ^= 1;
        }

#pragma unroll
        for (int nt = 0; nt < 4; nt++) {
            int n = n0 + wn * 32 + nt * 8 + tg * 2;
            if (n >= Vv) continue;
            float b0f = bf[n], b1f = bf[n + 1];
#pragma unroll
            for (int mt = 0; mt < 2; mt++) {
                int m = wm * 32 + mt * 16 + g;
                *(float2*)&preds[((size_t)m * Tv + t) * Vv + n] =
                    make_float2(c[mt][nt][0] + b0f, c[mt][nt][1] + b1f);
                *(float2*)&preds[((size_t)(m + 8) * Tv + t) * Vv + n] =
                    make_float2(c[mt][nt][2] + b0f, c[mt][nt][3] + b1f);
            }
        }
    } else {
        int q = blockIdx.x - 79;
        int n0 = (q & 7) * 64;
        int z = q >> 3;
        int kbase = z * DHCH;
        int tx = tid & 15, ty = tid >> 4;

        ull acc[2][4];
#pragma unroll
        for (int i = 0; i < 2; i++)
#pragma unroll
            for (int j = 0; j < 4; j++) acc[i][j] = 0ull;

#pragma unroll
        for (int r = 0; r < 4; r++) {
            int mm = ty + 16 * r;
            Xf[0][tx][mm] = g_h[mm * Dv + kbase + tx];
            Wf2[0][tx][mm] = decW[(size_t)(n0 + mm) * Dv + kbase + tx];
        }
        __syncthreads();
        int buf = 0;
        for (int k0 = 0; k0 < DHCH; k0 += 16) {
            float xr[4], wr[4];
            bool more = (k0 + 16 < DHCH);
            if (more) {
#pragma unroll
                for (int r = 0; r < 4; r++) {
                    int mm = ty + 16 * r;
                    xr[r] = g_h[mm * Dv + kbase + k0 + 16 + tx];
                    wr[r] = decW[(size_t)(n0 + mm) * Dv + kbase + k0 + 16 + tx];
                }
            }
#pragma unroll
            for (int k = 0; k < 16; k++) {
                ull a0 = *(const ull*)&Xf[buf][k][ty * 4];
                ull a1 = *(const ull*)&Xf[buf][k][ty * 4 + 2];
                float4 bq = *(const float4*)&Wf2[buf][k][tx * 4];
                ull bd0 = pk2(bq.x, bq.x), bd1 = pk2(bq.y, bq.y);
                ull bd2 = pk2(bq.z, bq.z), bd3 = pk2(bq.w, bq.w);
                fma2(acc[0][0], a0, bd0); fma2(acc[1][0], a1, bd0);
                fma2(acc[0][1], a0, bd1); fma2(acc[1][1], a1, bd1);
                fma2(acc[0][2], a0, bd2); fma2(acc[1][2], a1, bd2);
                fma2(acc[0][3], a0, bd3); fma2(acc[1][3], a1, bd3);
            }
            if (more) {
#pragma unroll
                for (int r = 0; r < 4; r++) {
                    int mm = ty + 16 * r;
                    Xf[buf ^ 1][tx][mm] = xr[r];
                    Wf2[buf ^ 1][tx][mm] = wr[r];
                }
            }
            __syncthreads();
            buf ^= 1;
        }
#pragma unroll
        for (int j = 0; j < 4; j++) {
            int n = n0 + tx * 4 + j;
            float bb = (z == 0) ? decb[n] : 0.0f;
#pragma unroll
            for (int i = 0; i < 2; i++) {
                float2 v = up2(acc[i][j]);
                int m = ty * 4 + 2 * i;
                g_dhp[z][m * Av + n] = v.x + bb;
                g_dhp[z][(m + 1) * Av + n] = v.y + bb;
            }
        }
    }
}

// --------------------------------- launcher ------------------------------------
extern "C" void kernel_launch(void* const* d_in, const int* in_sizes, int n_in,
                              void* d_out, int out_size) {
    const float* eo    = (const float*)d_in[0];
    const int*   caps  = (const int*)d_in[1];
    const float* emb   = (const float*)d_in[3];
    const float* encW  = (const float*)d_in[4];
    const float* encb  = (const float*)d_in[5];
    const float* decW  = (const float*)d_in[6];
    const float* decb  = (const float*)d_in[7];
    const float* fullW = (const float*)d_in[8];
    const float* fullb = (const float*)d_in[9];
    const float* ihW   = (const float*)d_in[10];
    const float* ihb   = (const float*)d_in[11];
    const float* icW   = (const float*)d_in[12];
    const float* icb   = (const float*)d_in[13];
    const float* Wih   = (const float*)d_in[14];
    const float* bih   = (const float*)d_in[15];
    const float* Whh   = (const float*)d_in[16];
    const float* bhh   = (const float*)d_in[17];
    const float* fcW   = (const float*)d_in[18];
    const float* fcb   = (const float*)d_in[19];

    float* preds  = (float*)d_out;
    float* alphas = preds + (size_t)Bv * Tv * Vv;

    k_zero_tail<<<(Bv * Vv + Bv * Pv + Bv * ENCv + 255) / 256, 256>>>(preds, alphas);
    k_cvtT<<<dim3(ENCv / 32, (Pv + 31) / 32, Bv), dim3(32, 8)>>>(eo);
    k_cvtW<<<(Av * ENCv / 4 + 255) / 256, 256>>>(encW);
    k_cvt_Wg<<<(G4D * KIN / 2 + 255) / 256, 256>>>(Wih, Whh);
    k_cvt_fcW<<<(NFCPAD * Dv / 2 + 255) / 256, 256>>>(fcW);
    k_cvt_emb<<<(2048 * Ev / 2 + 255) / 256, 256>>>(caps, emb);
    k_cvt_Wihe<<<(G4D * Ev / 2 + 255) / 256, 256>>>(Wih);
    k_init<<<(2 * Bv * Dv * 32 + 255) / 256, 256>>>(ihW, ihb, icW, icb);
    k_embW_mma<<<dim3(16, 16), 256>>>();
    k_encproj_mma<<<dim3(98, 4), 256>>>(encb);
    k_dh<<<dim3(8, DHZ), 256>>>(decW, decb);

    for (int t = 0; t < NSTEP; t++) {
        k_e<<<dim3(25, Bv), 256>>>(fullW, fullb);
        k_ctx<<<dim3(4, Bv), 256>>>(alphas, t);
        k_gates_mma<<<dim3(16, GZ), 256>>>();
        k_lstm<<<(Bv * Dv + 255) / 256, 256>>>(bih, bhh, t);
        k_fcdh<<<111, 256>>>(fcb, decW, decb, preds, t);
    }
}